// round 10
// baseline (speedup 1.0000x reference)
#include <cuda_runtime.h>

#define HU      64
#define G4      256
#define T_STEPS 256
#define BATCH   4096
#define BP      4116        // padded batch = 147 * 28 (pad rows never written: zero xz)
#define BB      28          // batch rows per K2 block (bt=7 per thread-group row)
#define K2_NTH  256
#define K2_GRID 147
#define K1_BT   128
#define K1_NTH  256
#define K1_TT   4

typedef unsigned long long u64;

// ~1.05 GB scratch: xz = x@W1 + b1, layout [t][j][b] with padded batch stride BP.
// Pad columns [4096,4116) are never written -> stay zero (static init) -> phantom
// rows evolve with xz=0, stay finite, and are never stored to out.
__device__ float XZ[(size_t)T_STEPS * G4 * BP];

__device__ __forceinline__ u64 fma2(u64 a, u64 b, u64 c) {
    u64 d;
    asm("fma.rn.f32x2 %0, %1, %2, %3;" : "=l"(d) : "l"(a), "l"(b), "l"(c));
    return d;
}
__device__ __forceinline__ float hadd2(u64 v) {
    float l, h;
    asm("mov.b64 {%0, %1}, %2;" : "=f"(l), "=f"(h) : "l"(v));
    return l + h;
}
__device__ __forceinline__ float fexp(float x) {
    float y;
    asm("ex2.approx.f32 %0, %1;" : "=f"(y) : "f"(x * 1.4426950408889634f));
    return y;
}
__device__ __forceinline__ float frcp(float x) {
    float y;
    asm("rcp.approx.f32 %0, %1;" : "=f"(y) : "f"(x));
    return y;
}
__device__ __forceinline__ float sigf(float x) { return frcp(1.0f + fexp(-x)); }
__device__ __forceinline__ float tanhfast(float x) {
    return fmaf(2.0f, frcp(1.0f + fexp(-2.0f * x)), -1.0f);
}

// ===================== K1: xz prepass, writes [t][j][b] (stride BP) =====================
__global__ void __launch_bounds__(K1_NTH)
k1_xz(const float* __restrict__ x, const float* __restrict__ W1,
      const float* __restrict__ b1)
{
    extern __shared__ __align__(16) float sm1[];
    float* W1p = sm1;               // 8192 floats (k4-packed transpose)
    float* xs  = sm1 + 8192;        // 128 rows * 128 floats (4t x 32f)

    const int tid = threadIdx.x;
    const int b0  = blockIdx.x * K1_BT;
    const int t0  = blockIdx.y * K1_TT;

    for (int i = tid; i < 32 * G4; i += K1_NTH) {
        int f = i >> 8, j = i & 255;
        W1p[((f >> 2) << 10) + (j << 2) + (f & 3)] = W1[i];
    }
    for (int i = tid; i < K1_BT * 32; i += K1_NTH) {   // 4096 float4
        int row = i >> 5, q = i & 31;
        ((float4*)xs)[(row << 5) + q] =
            *(const float4*)(x + ((size_t)(b0 + row) * T_STEPS + t0) * 32 + q * 4);
    }
    __syncthreads();

    const int u  = tid & 63;
    const int bg = tid >> 6;
    float bj[4];
#pragma unroll
    for (int jj = 0; jj < 4; jj++) bj[jj] = b1[u + 64 * jj];

    for (int tt = 0; tt < K1_TT; tt++) {
        const int t = t0 + tt;
        for (int rep = 0; rep < 4; rep++) {
            const int rb = bg * 32 + rep * 8;
            u64 acc[4][8];
#pragma unroll
            for (int jj = 0; jj < 4; jj++)
#pragma unroll
                for (int b = 0; b < 8; b++) acc[jj][b] = 0ULL;

#pragma unroll
            for (int f4 = 0; f4 < 8; f4++) {
                u64 w[4][2];
#pragma unroll
                for (int jj = 0; jj < 4; jj++) {
                    ulonglong2 W = *(const ulonglong2*)&W1p[(f4 << 10) + ((u + 64 * jj) << 2)];
                    w[jj][0] = W.x; w[jj][1] = W.y;
                }
#pragma unroll
                for (int b = 0; b < 8; b++) {
                    ulonglong2 X = *(const ulonglong2*)&xs[((rb + b) << 7) + (tt << 5) + (f4 << 2)];
#pragma unroll
                    for (int jj = 0; jj < 4; jj++) {
                        acc[jj][b] = fma2(X.x, w[jj][0], acc[jj][b]);
                        acc[jj][b] = fma2(X.y, w[jj][1], acc[jj][b]);
                    }
                }
            }
#pragma unroll
            for (int jj = 0; jj < 4; jj++) {
                float z[8];
#pragma unroll
                for (int b = 0; b < 8; b++) z[b] = hadd2(acc[jj][b]) + bj[jj];
                float4* dst = (float4*)&XZ[((size_t)t * G4 + u + 64 * jj) * BP + b0 + rb];
                dst[0] = make_float4(z[0], z[1], z[2], z[3]);
                dst[1] = make_float4(z[4], z[5], z[6], z[7]);
            }
        }
    }
}

// ===================== K2: fused 2-layer recurrence + dense heads =====================
// 147 blocks x 256 threads. u = tid&63 (unit, 4 gate cols), bg = tid>>6, bt=7 rows.
// One barrier per timestep (post-phase1); post-phase2 barrier removable (see R9).
#define K2_SMF 57344

__global__ void __launch_bounds__(K2_NTH, 1)
k2_main(const float* __restrict__ U1, const float* __restrict__ W2,
        const float* __restrict__ U2, const float* __restrict__ b2,
        const float* __restrict__ Wd, const float* __restrict__ bd,
        const float* __restrict__ Wo, const float* __restrict__ bo,
        float* __restrict__ out)
{
    extern __shared__ __align__(16) float sm[];
    float* U1p = sm;
    float* W2p = sm + 16384;
    float* U2p = sm + 32768;
    float* h1s = sm + 49152;       // [2][32][64] (28 rows used)
    float* h2s = sm + 53248;

    const int tid = threadIdx.x;

    for (int i = tid; i < HU * G4; i += K2_NTH) {
        int k = i >> 8, j = i & 255;
        int d = ((k >> 2) << 10) + (j << 2) + (k & 3);
        float a = U1[i], b = W2[i], c = U2[i];
        U1p[d] = a; W2p[d] = b; U2p[d] = c;
    }
    for (int i = tid; i < 4096; i += K2_NTH) { h1s[i] = 0.0f; h2s[i] = 0.0f; }

    const int u   = tid & 63;
    const int bg  = tid >> 6;
    const int b0g = bg * 7;
    const int bglob = blockIdx.x * BB;

    float b2j[4];
#pragma unroll
    for (int jj = 0; jj < 4; jj++) b2j[jj] = b2[u + 64 * jj];

    float c1[7], c2[7];
#pragma unroll
    for (int b = 0; b < 7; b++) { c1[b] = 0.0f; c2[b] = 0.0f; }

    // preload xz for t=0 (28 scalar loads; bt=7 breaks float4 alignment)
    float xr[4][7];
#pragma unroll
    for (int jj = 0; jj < 4; jj++) {
        const float* p = &XZ[((size_t)(u + 64 * jj)) * BP + bglob + b0g];
#pragma unroll
        for (int b = 0; b < 7; b++) xr[jj][b] = __ldg(p + b);
    }

    __syncthreads();

    int cur = 0;
    for (int t = 0; t < T_STEPS; t++) {
        const int nxt = cur ^ 1;

        // ---------- phase 1: z1 = xz + h1(t-1) @ U1 ; update c1, h1 ----------
        {
            u64 acc[4][7];
#pragma unroll
            for (int jj = 0; jj < 4; jj++)
#pragma unroll
                for (int b = 0; b < 7; b++) acc[jj][b] = 0ULL;

#pragma unroll 8
            for (int k4 = 0; k4 < 16; k4++) {
                u64 w[4][2];
#pragma unroll
                for (int jj = 0; jj < 4; jj++) {
                    ulonglong2 W = *(const ulonglong2*)&U1p[(k4 << 10) + ((u + 64 * jj) << 2)];
                    w[jj][0] = W.x; w[jj][1] = W.y;
                }
#pragma unroll
                for (int b = 0; b < 7; b++) {
                    ulonglong2 H = *(const ulonglong2*)&h1s[((cur << 5) + b0g + b) * 64 + (k4 << 2)];
#pragma unroll
                    for (int jj = 0; jj < 4; jj++) {
                        acc[jj][b] = fma2(H.x, w[jj][0], acc[jj][b]);
                        acc[jj][b] = fma2(H.y, w[jj][1], acc[jj][b]);
                    }
                }
            }

            float z[4][7];
#pragma unroll
            for (int jj = 0; jj < 4; jj++)
#pragma unroll
                for (int b = 0; b < 7; b++) z[jj][b] = hadd2(acc[jj][b]) + xr[jj][b];
#pragma unroll
            for (int b = 0; b < 7; b++) {
                c1[b] = sigf(z[1][b]) * c1[b] + sigf(z[0][b]) * tanhfast(z[2][b]);
                h1s[((nxt << 5) + b0g + b) * 64 + u] = sigf(z[3][b]) * tanhfast(c1[b]);
            }
        }
        __syncthreads();

        // ---------- phase 2: z2 = h1(t)@W2 + h2(t-1)@U2 + b2 ; update c2, h2 ----------
        {
            // prefetch next step's xz (consumed after next barrier)
            const int tn = (t + 1) & 255;
#pragma unroll
            for (int jj = 0; jj < 4; jj++) {
                const float* p = &XZ[((size_t)tn * G4 + u + 64 * jj) * BP + bglob + b0g];
#pragma unroll
                for (int b = 0; b < 7; b++) xr[jj][b] = __ldg(p + b);
            }

            u64 acc[4][7];
#pragma unroll
            for (int jj = 0; jj < 4; jj++)
#pragma unroll
                for (int b = 0; b < 7; b++) acc[jj][b] = 0ULL;

#pragma unroll 4
            for (int k4 = 0; k4 < 16; k4++) {
                u64 w2[4][2], v2[4][2];
#pragma unroll
                for (int jj = 0; jj < 4; jj++) {
                    ulonglong2 W = *(const ulonglong2*)&W2p[(k4 << 10) + ((u + 64 * jj) << 2)];
                    w2[jj][0] = W.x; w2[jj][1] = W.y;
                    ulonglong2 V = *(const ulonglong2*)&U2p[(k4 << 10) + ((u + 64 * jj) << 2)];
                    v2[jj][0] = V.x; v2[jj][1] = V.y;
                }
#pragma unroll
                for (int b = 0; b < 7; b++) {
                    ulonglong2 Hn = *(const ulonglong2*)&h1s[((nxt << 5) + b0g + b) * 64 + (k4 << 2)];
                    ulonglong2 Ho = *(const ulonglong2*)&h2s[((cur << 5) + b0g + b) * 64 + (k4 << 2)];
#pragma unroll
                    for (int jj = 0; jj < 4; jj++) {
                        acc[jj][b] = fma2(Hn.x, w2[jj][0], acc[jj][b]);
                        acc[jj][b] = fma2(Hn.y, w2[jj][1], acc[jj][b]);
                        acc[jj][b] = fma2(Ho.x, v2[jj][0], acc[jj][b]);
                        acc[jj][b] = fma2(Ho.y, v2[jj][1], acc[jj][b]);
                    }
                }
            }

            float z[4][7];
#pragma unroll
            for (int jj = 0; jj < 4; jj++)
#pragma unroll
                for (int b = 0; b < 7; b++) z[jj][b] = hadd2(acc[jj][b]) + b2j[jj];
#pragma unroll
            for (int b = 0; b < 7; b++) {
                c2[b] = sigf(z[1][b]) * c2[b] + sigf(z[0][b]) * tanhfast(z[2][b]);
                h2s[((nxt << 5) + b0g + b) * 64 + u] = sigf(z[3][b]) * tanhfast(c2[b]);
            }
        }

        cur = nxt;
    }
    __syncthreads();   // fence last phase-2 h2 writes before dense heads

    // final h2 in parity 0
    // ---------- dense head 1: d = sigmoid(h2 @ Wd + bd) -> stash in h1s ----------
    {
        const float bdv = bd[u];
#pragma unroll
        for (int b = 0; b < 7; b++) {
            float a = bdv;
#pragma unroll 8
            for (int k = 0; k < HU; k++)
                a += h2s[(b0g + b) * 64 + k] * Wd[k * HU + u];
            h1s[(b0g + b) * 64 + u] = sigf(a);
        }
    }
    __syncthreads();
    // ---------- dense head 2: out = sigmoid(d @ Wo + bo), warp per 4 rows ----------
    {
        const int w  = tid >> 5;
        const int ln = tid & 31;
        const float bov = bo[0];
        const float wo0 = Wo[ln], wo1 = Wo[ln + 32];
#pragma unroll
        for (int r = 0; r < 4; r++) {
            int row = w * 4 + r;
            if (row < BB) {
                float p = h1s[row * 64 + ln] * wo0 + h1s[row * 64 + ln + 32] * wo1;
#pragma unroll
                for (int s = 16; s; s >>= 1)
                    p += __shfl_xor_sync(0xffffffffu, p, s);
                int grow = bglob + row;
                if (ln == 0 && grow < BATCH)
                    out[grow] = sigf(p + bov);
            }
        }
    }
}

extern "C" void kernel_launch(void* const* d_in, const int* in_sizes, int n_in,
                              void* d_out, int out_size)
{
    const float* x  = (const float*)d_in[0];
    const float* W1 = (const float*)d_in[1];
    const float* U1 = (const float*)d_in[2];
    const float* b1 = (const float*)d_in[3];
    const float* W2 = (const float*)d_in[4];
    const float* U2 = (const float*)d_in[5];
    const float* b2 = (const float*)d_in[6];
    const float* Wd = (const float*)d_in[7];
    const float* bd = (const float*)d_in[8];
    const float* Wo = (const float*)d_in[9];
    const float* bo = (const float*)d_in[10];
    float* out = (float*)d_out;

    // K1: xz prepass -> XZ[t][j][b] (stride BP; pad cols stay zero)
    const size_t k1_smem = (8192 + K1_BT * 32 * K1_TT) * sizeof(float);   // 96 KB
    cudaFuncSetAttribute(k1_xz, cudaFuncAttributeMaxDynamicSharedMemorySize, (int)k1_smem);
    dim3 g1(BATCH / K1_BT, T_STEPS / K1_TT);
    k1_xz<<<g1, K1_NTH, k1_smem>>>(x, W1, b1);

    // K2: fused recurrence, 147 blocks (full chip)
    const size_t k2_smem = (size_t)K2_SMF * sizeof(float);        // 229376 B
    cudaFuncSetAttribute(k2_main, cudaFuncAttributeMaxDynamicSharedMemorySize, (int)k2_smem);
    k2_main<<<K2_GRID, K2_NTH, k2_smem>>>(U1, W2, U2, b2, Wd, bd, Wo, bo, out);
}

// round 11
// speedup vs baseline: 1.1053x; 1.1053x over previous
#include <cuda_runtime.h>

#define HU      64
#define G4      256
#define T_STEPS 256
#define BATCH   4096
#define BB      32          // batch rows per K2 block
#define K2_NTH  512         // 256 = group A (layer1), 256 = group B (layer2)
#define K1_BT   128
#define K1_NTH  256
#define K1_TT   4

typedef unsigned long long u64;

// 1 GB scratch: xz = x@W1 + b1, layout [t][j][b]
__device__ float XZ[(size_t)T_STEPS * G4 * BATCH];

__device__ __forceinline__ u64 fma2(u64 a, u64 b, u64 c) {
    u64 d;
    asm("fma.rn.f32x2 %0, %1, %2, %3;" : "=l"(d) : "l"(a), "l"(b), "l"(c));
    return d;
}
__device__ __forceinline__ float hadd2(u64 v) {
    float l, h;
    asm("mov.b64 {%0, %1}, %2;" : "=f"(l), "=f"(h) : "l"(v));
    return l + h;
}
__device__ __forceinline__ float fexp(float x) {
    float y;
    asm("ex2.approx.f32 %0, %1;" : "=f"(y) : "f"(x * 1.4426950408889634f));
    return y;
}
__device__ __forceinline__ float frcp(float x) {
    float y;
    asm("rcp.approx.f32 %0, %1;" : "=f"(y) : "f"(x));
    return y;
}
__device__ __forceinline__ float sigf(float x) { return frcp(1.0f + fexp(-x)); }
__device__ __forceinline__ float tanhfast(float x) {
    return fmaf(2.0f, frcp(1.0f + fexp(-2.0f * x)), -1.0f);
}

// ===================== K1: xz prepass (R9 version), writes [t][j][b] =====================
__global__ void __launch_bounds__(K1_NTH)
k1_xz(const float* __restrict__ x, const float* __restrict__ W1,
      const float* __restrict__ b1)
{
    extern __shared__ __align__(16) float sm1[];
    float* W1p = sm1;               // 8192 floats (k4-packed transpose)
    float* xs  = sm1 + 8192;        // 128 rows * 128 floats (4t x 32f)

    const int tid = threadIdx.x;
    const int b0  = blockIdx.x * K1_BT;
    const int t0  = blockIdx.y * K1_TT;

    for (int i = tid; i < 32 * G4; i += K1_NTH) {
        int f = i >> 8, j = i & 255;
        W1p[((f >> 2) << 10) + (j << 2) + (f & 3)] = W1[i];
    }
    for (int i = tid; i < K1_BT * 32; i += K1_NTH) {   // 4096 float4
        int row = i >> 5, q = i & 31;
        ((float4*)xs)[(row << 5) + q] =
            *(const float4*)(x + ((size_t)(b0 + row) * T_STEPS + t0) * 32 + q * 4);
    }
    __syncthreads();

    const int u  = tid & 63;
    const int bg = tid >> 6;
    float bj[4];
#pragma unroll
    for (int jj = 0; jj < 4; jj++) bj[jj] = b1[u + 64 * jj];

    for (int tt = 0; tt < K1_TT; tt++) {
        const int t = t0 + tt;
        for (int rep = 0; rep < 4; rep++) {
            const int rb = bg * 32 + rep * 8;
            u64 acc[4][8];
#pragma unroll
            for (int jj = 0; jj < 4; jj++)
#pragma unroll
                for (int b = 0; b < 8; b++) acc[jj][b] = 0ULL;

#pragma unroll
            for (int f4 = 0; f4 < 8; f4++) {
                u64 w[4][2];
#pragma unroll
                for (int jj = 0; jj < 4; jj++) {
                    ulonglong2 W = *(const ulonglong2*)&W1p[(f4 << 10) + ((u + 64 * jj) << 2)];
                    w[jj][0] = W.x; w[jj][1] = W.y;
                }
#pragma unroll
                for (int b = 0; b < 8; b++) {
                    ulonglong2 X = *(const ulonglong2*)&xs[((rb + b) << 7) + (tt << 5) + (f4 << 2)];
#pragma unroll
                    for (int jj = 0; jj < 4; jj++) {
                        acc[jj][b] = fma2(X.x, w[jj][0], acc[jj][b]);
                        acc[jj][b] = fma2(X.y, w[jj][1], acc[jj][b]);
                    }
                }
            }
#pragma unroll
            for (int jj = 0; jj < 4; jj++) {
                float z[8];
#pragma unroll
                for (int b = 0; b < 8; b++) z[b] = hadd2(acc[jj][b]) + bj[jj];
                float4* dst = (float4*)&XZ[((size_t)t * G4 + u + 64 * jj) * BATCH + b0 + rb];
                dst[0] = make_float4(z[0], z[1], z[2], z[3]);
                dst[1] = make_float4(z[4], z[5], z[6], z[7]);
            }
        }
    }
}

// ===================== K2: warp-specialized pipelined recurrence =====================
// 512 threads. Group A (tid<256): layer 1 at step i. Group B (tid>=256): layer 2 at
// step i-1. One __syncthreads per iteration; slot-parity double buffers:
//   iter i, p=i&1, q=p^1:
//     A: reads h1[q] (=h1(i-1)), writes h1[p] (=h1(i))
//     B: reads h1[q] (=h1(i-1)), reads h2[p] (=h2(i-2)), writes h2[q] (=h2(i-1))
//   -> no same-array same-slot write/read races within an iteration.
// Final h2(255) lands in slot 1.
#define K2_SMF 57344

__global__ void __launch_bounds__(K2_NTH, 1)
k2_main(const float* __restrict__ U1, const float* __restrict__ W2,
        const float* __restrict__ U2, const float* __restrict__ b2,
        const float* __restrict__ Wd, const float* __restrict__ bd,
        const float* __restrict__ Wo, const float* __restrict__ bo,
        float* __restrict__ out)
{
    extern __shared__ __align__(16) float sm[];
    float* U1p = sm;                // 16384
    float* W2p = sm + 16384;        // 16384
    float* U2p = sm + 32768;        // 16384
    float* h1s = sm + 49152;        // [2][32][64] = 4096
    float* h2s = sm + 53248;        // [2][32][64] = 4096

    const int tid = threadIdx.x;

    for (int i = tid; i < HU * G4; i += K2_NTH) {
        int k = i >> 8, j = i & 255;
        int d = ((k >> 2) << 10) + (j << 2) + (k & 3);
        float a = U1[i], b = W2[i], c = U2[i];
        U1p[d] = a; W2p[d] = b; U2p[d] = c;
    }
    for (int i = tid; i < 4096; i += K2_NTH) { h1s[i] = 0.0f; h2s[i] = 0.0f; }

    const int grp    = tid >> 8;        // 0 = A (layer1), 1 = B (layer2)
    const int wg_tid = tid & 255;
    const int u      = wg_tid & 63;
    const int bg     = wg_tid >> 6;
    const int b0g    = bg * 8;
    const int bglob  = blockIdx.x * BB;

    float cst[8];                       // c1 for A, c2 for B
#pragma unroll
    for (int b = 0; b < 8; b++) cst[b] = 0.0f;

    float b2j[4];
#pragma unroll
    for (int jj = 0; jj < 4; jj++) b2j[jj] = b2[u + 64 * jj];   // used by B only

    __syncthreads();

    for (int i = 0; i <= T_STEPS; i++) {
        const int p = i & 1;
        const int q = p ^ 1;

        if (grp == 0) {
            // ---------------- group A: layer 1, step i ----------------
            if (i < T_STEPS) {
                // xz loads issued first; latency hidden under the U1 matvec
                float4 xa[4], xb[4];
#pragma unroll
                for (int jj = 0; jj < 4; jj++) {
                    const float* ptr = &XZ[((size_t)i * G4 + u + 64 * jj) * BATCH + bglob + b0g];
                    xa[jj] = *(const float4*)ptr;
                    xb[jj] = *(const float4*)(ptr + 4);
                }

                u64 acc[4][8];
#pragma unroll
                for (int jj = 0; jj < 4; jj++)
#pragma unroll
                    for (int b = 0; b < 8; b++) acc[jj][b] = 0ULL;

#pragma unroll 4
                for (int k4 = 0; k4 < 16; k4++) {
                    u64 w[4][2];
#pragma unroll
                    for (int jj = 0; jj < 4; jj++) {
                        ulonglong2 W = *(const ulonglong2*)&U1p[(k4 << 10) + ((u + 64 * jj) << 2)];
                        w[jj][0] = W.x; w[jj][1] = W.y;
                    }
#pragma unroll
                    for (int b = 0; b < 8; b++) {
                        ulonglong2 H = *(const ulonglong2*)&h1s[((q << 5) + b0g + b) * 64 + (k4 << 2)];
#pragma unroll
                        for (int jj = 0; jj < 4; jj++) {
                            acc[jj][b] = fma2(H.x, w[jj][0], acc[jj][b]);
                            acc[jj][b] = fma2(H.y, w[jj][1], acc[jj][b]);
                        }
                    }
                }

                float z[4][8];
#pragma unroll
                for (int jj = 0; jj < 4; jj++) {
#pragma unroll
                    for (int b = 0; b < 8; b++) z[jj][b] = hadd2(acc[jj][b]);
                    z[jj][0] += xa[jj].x; z[jj][1] += xa[jj].y;
                    z[jj][2] += xa[jj].z; z[jj][3] += xa[jj].w;
                    z[jj][4] += xb[jj].x; z[jj][5] += xb[jj].y;
                    z[jj][6] += xb[jj].z; z[jj][7] += xb[jj].w;
                }
#pragma unroll
                for (int b = 0; b < 8; b++) {
                    cst[b] = sigf(z[1][b]) * cst[b] + sigf(z[0][b]) * tanhfast(z[2][b]);
                    h1s[((p << 5) + b0g + b) * 64 + u] = sigf(z[3][b]) * tanhfast(cst[b]);
                }
            }
        } else {
            // ---------------- group B: layer 2, step i-1 ----------------
            if (i >= 1) {
                u64 acc[4][8];
#pragma unroll
                for (int jj = 0; jj < 4; jj++)
#pragma unroll
                    for (int b = 0; b < 8; b++) acc[jj][b] = 0ULL;

#pragma unroll 2
                for (int k4 = 0; k4 < 16; k4++) {
                    u64 w2[4][2], v2[4][2];
#pragma unroll
                    for (int jj = 0; jj < 4; jj++) {
                        ulonglong2 W = *(const ulonglong2*)&W2p[(k4 << 10) + ((u + 64 * jj) << 2)];
                        w2[jj][0] = W.x; w2[jj][1] = W.y;
                        ulonglong2 V = *(const ulonglong2*)&U2p[(k4 << 10) + ((u + 64 * jj) << 2)];
                        v2[jj][0] = V.x; v2[jj][1] = V.y;
                    }
#pragma unroll
                    for (int b = 0; b < 8; b++) {
                        ulonglong2 Hn = *(const ulonglong2*)&h1s[((q << 5) + b0g + b) * 64 + (k4 << 2)];
                        ulonglong2 Ho = *(const ulonglong2*)&h2s[((p << 5) + b0g + b) * 64 + (k4 << 2)];
#pragma unroll
                        for (int jj = 0; jj < 4; jj++) {
                            acc[jj][b] = fma2(Hn.x, w2[jj][0], acc[jj][b]);
                            acc[jj][b] = fma2(Hn.y, w2[jj][1], acc[jj][b]);
                            acc[jj][b] = fma2(Ho.x, v2[jj][0], acc[jj][b]);
                            acc[jj][b] = fma2(Ho.y, v2[jj][1], acc[jj][b]);
                        }
                    }
                }

                float z[4][8];
#pragma unroll
                for (int jj = 0; jj < 4; jj++)
#pragma unroll
                    for (int b = 0; b < 8; b++) z[jj][b] = hadd2(acc[jj][b]) + b2j[jj];
#pragma unroll
                for (int b = 0; b < 8; b++) {
                    cst[b] = sigf(z[1][b]) * cst[b] + sigf(z[0][b]) * tanhfast(z[2][b]);
                    h2s[((q << 5) + b0g + b) * 64 + u] = sigf(z[3][b]) * tanhfast(cst[b]);
                }
            }
        }
        __syncthreads();
    }

    // final h2(255) in slot 1: h2s[(32 + row)*64 + k]
    // ---------- dense head 1: d = sigmoid(h2 @ Wd + bd) -> h1s slot 0 ----------
    {
        const int rg  = tid >> 6;      // 0..7
        const int uu  = tid & 63;
        const float bdv = bd[uu];
#pragma unroll
        for (int r = 0; r < 4; r++) {
            int row = rg * 4 + r;
            float a = bdv;
#pragma unroll 8
            for (int k = 0; k < HU; k++)
                a += h2s[(32 + row) * 64 + k] * Wd[k * HU + uu];
            h1s[row * 64 + uu] = sigf(a);
        }
    }
    __syncthreads();
    // ---------- dense head 2: out = sigmoid(d @ Wo + bo), 16 warps x 2 rows ----------
    {
        const int w  = tid >> 5;       // 0..15
        const int ln = tid & 31;
        const float bov = bo[0];
        const float wo0 = Wo[ln], wo1 = Wo[ln + 32];
#pragma unroll
        for (int r = 0; r < 2; r++) {
            int row = w * 2 + r;
            float pv = h1s[row * 64 + ln] * wo0 + h1s[row * 64 + ln + 32] * wo1;
#pragma unroll
            for (int s = 16; s; s >>= 1)
                pv += __shfl_xor_sync(0xffffffffu, pv, s);
            if (ln == 0)
                out[bglob + row] = sigf(pv + bov);
        }
    }
}

extern "C" void kernel_launch(void* const* d_in, const int* in_sizes, int n_in,
                              void* d_out, int out_size)
{
    const float* x  = (const float*)d_in[0];
    const float* W1 = (const float*)d_in[1];
    const float* U1 = (const float*)d_in[2];
    const float* b1 = (const float*)d_in[3];
    const float* W2 = (const float*)d_in[4];
    const float* U2 = (const float*)d_in[5];
    const float* b2 = (const float*)d_in[6];
    const float* Wd = (const float*)d_in[7];
    const float* bd = (const float*)d_in[8];
    const float* Wo = (const float*)d_in[9];
    const float* bo = (const float*)d_in[10];
    float* out = (float*)d_out;

    // K1: xz prepass -> XZ[t][j][b]
    const size_t k1_smem = (8192 + K1_BT * 32 * K1_TT) * sizeof(float);   // 96 KB
    cudaFuncSetAttribute(k1_xz, cudaFuncAttributeMaxDynamicSharedMemorySize, (int)k1_smem);
    dim3 g1(BATCH / K1_BT, T_STEPS / K1_TT);
    k1_xz<<<g1, K1_NTH, k1_smem>>>(x, W1, b1);

    // K2: warp-specialized pipelined recurrence
    const size_t k2_smem = (size_t)K2_SMF * sizeof(float);        // 229376 B
    cudaFuncSetAttribute(k2_main, cudaFuncAttributeMaxDynamicSharedMemorySize, (int)k2_smem);
    k2_main<<<BATCH / BB, K2_NTH, k2_smem>>>(U1, W2, U2, b2, Wd, bd, Wo, bo, out);
}

// round 12
// speedup vs baseline: 1.1086x; 1.0031x over previous
#include <cuda_runtime.h>

#define HU      64
#define G4      256
#define T_STEPS 256
#define BATCH   4096
#define BB      32          // batch rows per K2 block
#define K2_NTH  512         // 256 = group A (layer1), 256 = group B (layer2)
#define K1_BT   128
#define K1_NTH  256
#define K1_TT   4

typedef unsigned long long u64;

// 1 GB scratch: xz = x@W1 + b1, layout [t][j][b]
__device__ float XZ[(size_t)T_STEPS * G4 * BATCH];

__device__ __forceinline__ u64 fma2(u64 a, u64 b, u64 c) {
    u64 d;
    asm("fma.rn.f32x2 %0, %1, %2, %3;" : "=l"(d) : "l"(a), "l"(b), "l"(c));
    return d;
}
__device__ __forceinline__ float hadd2(u64 v) {
    float l, h;
    asm("mov.b64 {%0, %1}, %2;" : "=f"(l), "=f"(h) : "l"(v));
    return l + h;
}
__device__ __forceinline__ float fexp(float x) {
    float y;
    asm("ex2.approx.f32 %0, %1;" : "=f"(y) : "f"(x * 1.4426950408889634f));
    return y;
}
__device__ __forceinline__ float frcp(float x) {
    float y;
    asm("rcp.approx.f32 %0, %1;" : "=f"(y) : "f"(x));
    return y;
}
__device__ __forceinline__ float sigf(float x) { return frcp(1.0f + fexp(-x)); }
__device__ __forceinline__ float tanhfast(float x) {
    return fmaf(2.0f, frcp(1.0f + fexp(-2.0f * x)), -1.0f);
}

// ===================== K1: xz prepass (R9 version), writes [t][j][b] =====================
__global__ void __launch_bounds__(K1_NTH)
k1_xz(const float* __restrict__ x, const float* __restrict__ W1,
      const float* __restrict__ b1)
{
    extern __shared__ __align__(16) float sm1[];
    float* W1p = sm1;               // 8192 floats (k4-packed transpose)
    float* xs  = sm1 + 8192;        // 128 rows * 128 floats (4t x 32f)

    const int tid = threadIdx.x;
    const int b0  = blockIdx.x * K1_BT;
    const int t0  = blockIdx.y * K1_TT;

    for (int i = tid; i < 32 * G4; i += K1_NTH) {
        int f = i >> 8, j = i & 255;
        W1p[((f >> 2) << 10) + (j << 2) + (f & 3)] = W1[i];
    }
    for (int i = tid; i < K1_BT * 32; i += K1_NTH) {   // 4096 float4
        int row = i >> 5, q = i & 31;
        ((float4*)xs)[(row << 5) + q] =
            *(const float4*)(x + ((size_t)(b0 + row) * T_STEPS + t0) * 32 + q * 4);
    }
    __syncthreads();

    const int u  = tid & 63;
    const int bg = tid >> 6;
    float bj[4];
#pragma unroll
    for (int jj = 0; jj < 4; jj++) bj[jj] = b1[u + 64 * jj];

    for (int tt = 0; tt < K1_TT; tt++) {
        const int t = t0 + tt;
        for (int rep = 0; rep < 4; rep++) {
            const int rb = bg * 32 + rep * 8;
            u64 acc[4][8];
#pragma unroll
            for (int jj = 0; jj < 4; jj++)
#pragma unroll
                for (int b = 0; b < 8; b++) acc[jj][b] = 0ULL;

#pragma unroll
            for (int f4 = 0; f4 < 8; f4++) {
                u64 w[4][2];
#pragma unroll
                for (int jj = 0; jj < 4; jj++) {
                    ulonglong2 W = *(const ulonglong2*)&W1p[(f4 << 10) + ((u + 64 * jj) << 2)];
                    w[jj][0] = W.x; w[jj][1] = W.y;
                }
#pragma unroll
                for (int b = 0; b < 8; b++) {
                    ulonglong2 X = *(const ulonglong2*)&xs[((rb + b) << 7) + (tt << 5) + (f4 << 2)];
#pragma unroll
                    for (int jj = 0; jj < 4; jj++) {
                        acc[jj][b] = fma2(X.x, w[jj][0], acc[jj][b]);
                        acc[jj][b] = fma2(X.y, w[jj][1], acc[jj][b]);
                    }
                }
            }
#pragma unroll
            for (int jj = 0; jj < 4; jj++) {
                float z[8];
#pragma unroll
                for (int b = 0; b < 8; b++) z[b] = hadd2(acc[jj][b]) + bj[jj];
                float4* dst = (float4*)&XZ[((size_t)t * G4 + u + 64 * jj) * BATCH + b0 + rb];
                dst[0] = make_float4(z[0], z[1], z[2], z[3]);
                dst[1] = make_float4(z[4], z[5], z[6], z[7]);
            }
        }
    }
}

// ===================== K2: warp-specialized pipelined recurrence =====================
// 512 threads. Group A (tid<256): layer 1 at step i. Group B (tid>=256): layer 2 at
// step i-1. One __syncthreads per iteration; slot-parity double buffers:
//   iter i, p=i&1, q=p^1:
//     A: reads h1[q] (=h1(i-1)), writes h1[p] (=h1(i))
//     B: reads h1[q] (=h1(i-1)), reads h2[p] (=h2(i-2)), writes h2[q] (=h2(i-1))
//   -> no same-array same-slot write/read races within an iteration.
// Final h2(255) lands in slot 1.
#define K2_SMF 57344

__global__ void __launch_bounds__(K2_NTH, 1)
k2_main(const float* __restrict__ U1, const float* __restrict__ W2,
        const float* __restrict__ U2, const float* __restrict__ b2,
        const float* __restrict__ Wd, const float* __restrict__ bd,
        const float* __restrict__ Wo, const float* __restrict__ bo,
        float* __restrict__ out)
{
    extern __shared__ __align__(16) float sm[];
    float* U1p = sm;                // 16384
    float* W2p = sm + 16384;        // 16384
    float* U2p = sm + 32768;        // 16384
    float* h1s = sm + 49152;        // [2][32][64] = 4096
    float* h2s = sm + 53248;        // [2][32][64] = 4096

    const int tid = threadIdx.x;

    for (int i = tid; i < HU * G4; i += K2_NTH) {
        int k = i >> 8, j = i & 255;
        int d = ((k >> 2) << 10) + (j << 2) + (k & 3);
        float a = U1[i], b = W2[i], c = U2[i];
        U1p[d] = a; W2p[d] = b; U2p[d] = c;
    }
    for (int i = tid; i < 4096; i += K2_NTH) { h1s[i] = 0.0f; h2s[i] = 0.0f; }

    const int grp    = tid >> 8;        // 0 = A (layer1), 1 = B (layer2)
    const int wg_tid = tid & 255;
    const int u      = wg_tid & 63;
    const int bg     = wg_tid >> 6;
    const int b0g    = bg * 8;
    const int bglob  = blockIdx.x * BB;

    float cst[8];                       // c1 for A, c2 for B
#pragma unroll
    for (int b = 0; b < 8; b++) cst[b] = 0.0f;

    float b2j[4];
#pragma unroll
    for (int jj = 0; jj < 4; jj++) b2j[jj] = b2[u + 64 * jj];   // used by B only

    __syncthreads();

    for (int i = 0; i <= T_STEPS; i++) {
        const int p = i & 1;
        const int q = p ^ 1;

        if (grp == 0) {
            // ---------------- group A: layer 1, step i ----------------
            if (i < T_STEPS) {
                // xz loads issued first; latency hidden under the U1 matvec
                float4 xa[4], xb[4];
#pragma unroll
                for (int jj = 0; jj < 4; jj++) {
                    const float* ptr = &XZ[((size_t)i * G4 + u + 64 * jj) * BATCH + bglob + b0g];
                    xa[jj] = *(const float4*)ptr;
                    xb[jj] = *(const float4*)(ptr + 4);
                }

                u64 acc[4][8];
#pragma unroll
                for (int jj = 0; jj < 4; jj++)
#pragma unroll
                    for (int b = 0; b < 8; b++) acc[jj][b] = 0ULL;

#pragma unroll 4
                for (int k4 = 0; k4 < 16; k4++) {
                    u64 w[4][2];
#pragma unroll
                    for (int jj = 0; jj < 4; jj++) {
                        ulonglong2 W = *(const ulonglong2*)&U1p[(k4 << 10) + ((u + 64 * jj) << 2)];
                        w[jj][0] = W.x; w[jj][1] = W.y;
                    }
#pragma unroll
                    for (int b = 0; b < 8; b++) {
                        ulonglong2 H = *(const ulonglong2*)&h1s[((q << 5) + b0g + b) * 64 + (k4 << 2)];
#pragma unroll
                        for (int jj = 0; jj < 4; jj++) {
                            acc[jj][b] = fma2(H.x, w[jj][0], acc[jj][b]);
                            acc[jj][b] = fma2(H.y, w[jj][1], acc[jj][b]);
                        }
                    }
                }

                float z[4][8];
#pragma unroll
                for (int jj = 0; jj < 4; jj++) {
#pragma unroll
                    for (int b = 0; b < 8; b++) z[jj][b] = hadd2(acc[jj][b]);
                    z[jj][0] += xa[jj].x; z[jj][1] += xa[jj].y;
                    z[jj][2] += xa[jj].z; z[jj][3] += xa[jj].w;
                    z[jj][4] += xb[jj].x; z[jj][5] += xb[jj].y;
                    z[jj][6] += xb[jj].z; z[jj][7] += xb[jj].w;
                }
#pragma unroll
                for (int b = 0; b < 8; b++) {
                    cst[b] = sigf(z[1][b]) * cst[b] + sigf(z[0][b]) * tanhfast(z[2][b]);
                    h1s[((p << 5) + b0g + b) * 64 + u] = sigf(z[3][b]) * tanhfast(cst[b]);
                }
            }
        } else {
            // ---------------- group B: layer 2, step i-1 ----------------
            if (i >= 1) {
                u64 acc[4][8];
#pragma unroll
                for (int jj = 0; jj < 4; jj++)
#pragma unroll
                    for (int b = 0; b < 8; b++) acc[jj][b] = 0ULL;

#pragma unroll 2
                for (int k4 = 0; k4 < 16; k4++) {
                    u64 w2[4][2], v2[4][2];
#pragma unroll
                    for (int jj = 0; jj < 4; jj++) {
                        ulonglong2 W = *(const ulonglong2*)&W2p[(k4 << 10) + ((u + 64 * jj) << 2)];
                        w2[jj][0] = W.x; w2[jj][1] = W.y;
                        ulonglong2 V = *(const ulonglong2*)&U2p[(k4 << 10) + ((u + 64 * jj) << 2)];
                        v2[jj][0] = V.x; v2[jj][1] = V.y;
                    }
#pragma unroll
                    for (int b = 0; b < 8; b++) {
                        ulonglong2 Hn = *(const ulonglong2*)&h1s[((q << 5) + b0g + b) * 64 + (k4 << 2)];
                        ulonglong2 Ho = *(const ulonglong2*)&h2s[((p << 5) + b0g + b) * 64 + (k4 << 2)];
#pragma unroll
                        for (int jj = 0; jj < 4; jj++) {
                            acc[jj][b] = fma2(Hn.x, w2[jj][0], acc[jj][b]);
                            acc[jj][b] = fma2(Hn.y, w2[jj][1], acc[jj][b]);
                            acc[jj][b] = fma2(Ho.x, v2[jj][0], acc[jj][b]);
                            acc[jj][b] = fma2(Ho.y, v2[jj][1], acc[jj][b]);
                        }
                    }
                }

                float z[4][8];
#pragma unroll
                for (int jj = 0; jj < 4; jj++)
#pragma unroll
                    for (int b = 0; b < 8; b++) z[jj][b] = hadd2(acc[jj][b]) + b2j[jj];
#pragma unroll
                for (int b = 0; b < 8; b++) {
                    cst[b] = sigf(z[1][b]) * cst[b] + sigf(z[0][b]) * tanhfast(z[2][b]);
                    h2s[((q << 5) + b0g + b) * 64 + u] = sigf(z[3][b]) * tanhfast(cst[b]);
                }
            }
        }
        __syncthreads();
    }

    // final h2(255) in slot 1: h2s[(32 + row)*64 + k]
    // ---------- dense head 1: d = sigmoid(h2 @ Wd + bd) -> h1s slot 0 ----------
    {
        const int rg  = tid >> 6;      // 0..7
        const int uu  = tid & 63;
        const float bdv = bd[uu];
#pragma unroll
        for (int r = 0; r < 4; r++) {
            int row = rg * 4 + r;
            float a = bdv;
#pragma unroll 8
            for (int k = 0; k < HU; k++)
                a += h2s[(32 + row) * 64 + k] * Wd[k * HU + uu];
            h1s[row * 64 + uu] = sigf(a);
        }
    }
    __syncthreads();
    // ---------- dense head 2: out = sigmoid(d @ Wo + bo), 16 warps x 2 rows ----------
    {
        const int w  = tid >> 5;       // 0..15
        const int ln = tid & 31;
        const float bov = bo[0];
        const float wo0 = Wo[ln], wo1 = Wo[ln + 32];
#pragma unroll
        for (int r = 0; r < 2; r++) {
            int row = w * 2 + r;
            float pv = h1s[row * 64 + ln] * wo0 + h1s[row * 64 + ln + 32] * wo1;
#pragma unroll
            for (int s = 16; s; s >>= 1)
                pv += __shfl_xor_sync(0xffffffffu, pv, s);
            if (ln == 0)
                out[bglob + row] = sigf(pv + bov);
        }
    }
}

extern "C" void kernel_launch(void* const* d_in, const int* in_sizes, int n_in,
                              void* d_out, int out_size)
{
    const float* x  = (const float*)d_in[0];
    const float* W1 = (const float*)d_in[1];
    const float* U1 = (const float*)d_in[2];
    const float* b1 = (const float*)d_in[3];
    const float* W2 = (const float*)d_in[4];
    const float* U2 = (const float*)d_in[5];
    const float* b2 = (const float*)d_in[6];
    const float* Wd = (const float*)d_in[7];
    const float* bd = (const float*)d_in[8];
    const float* Wo = (const float*)d_in[9];
    const float* bo = (const float*)d_in[10];
    float* out = (float*)d_out;

    // K1: xz prepass -> XZ[t][j][b]
    const size_t k1_smem = (8192 + K1_BT * 32 * K1_TT) * sizeof(float);   // 96 KB
    cudaFuncSetAttribute(k1_xz, cudaFuncAttributeMaxDynamicSharedMemorySize, (int)k1_smem);
    dim3 g1(BATCH / K1_BT, T_STEPS / K1_TT);
    k1_xz<<<g1, K1_NTH, k1_smem>>>(x, W1, b1);

    // K2: warp-specialized pipelined recurrence
    const size_t k2_smem = (size_t)K2_SMF * sizeof(float);        // 229376 B
    cudaFuncSetAttribute(k2_main, cudaFuncAttributeMaxDynamicSharedMemorySize, (int)k2_smem);
    k2_main<<<BATCH / BB, K2_NTH, k2_smem>>>(U1, W2, U2, b2, Wd, bd, Wo, bo, out);
}

// round 13
// speedup vs baseline: 2.5227x; 2.2755x over previous
#include <cuda_runtime.h>
#include <cuda_bf16.h>

#define T_STEPS 256
#define BATCH   4096
#define BB      32
#define NTH     256
#define SMEM_BYTES 221184

// smem byte offsets
#define U1LO 0        // [256 n][64 k] bf16, 128B rows, swizzled (lo part of U1)
#define W2LO 32768
#define U2LO 65536
#define W1HI 98304    // [256 n][32 k] bf16, 128B rows
#define W1LO 131072
#define H1HI 163840   // [2 parity][32 r][64 k] bf16 (4096 B per parity)
#define H1LO 172032
#define H2HI 180224
#define H2LO 188416
#define XHI  196608   // [2 parity][32 r][32 k] bf16, 128B rows
#define XLO  204800
#define H2F  212992   // [32][64] fp32 final h2 (8192 B)

__device__ __forceinline__ unsigned swz(unsigned off) { return off ^ ((off >> 3) & 0x70); }
__device__ __forceinline__ unsigned lds32(const char* sm, unsigned base, int r, int k) {
    return *(const unsigned*)(sm + base + swz((unsigned)(r * 128 + k * 2)));
}
__device__ __forceinline__ void sts32(char* sm, unsigned base, int r, int k, unsigned v) {
    *(unsigned*)(sm + base + swz((unsigned)(r * 128 + k * 2))) = v;
}
__device__ __forceinline__ unsigned pack2(float e0, float e1) {   // e0 -> low half
    unsigned r;
    asm("cvt.rn.bf16x2.f32 %0, %1, %2;" : "=r"(r) : "f"(e1), "f"(e0));
    return r;
}
__device__ __forceinline__ float bfv(float v) { return __bfloat162float(__float2bfloat16(v)); }
__device__ __forceinline__ float fexp(float x) {
    float y; asm("ex2.approx.f32 %0, %1;" : "=f"(y) : "f"(x * 1.4426950408889634f)); return y;
}
__device__ __forceinline__ float frcp(float x) {
    float y; asm("rcp.approx.f32 %0, %1;" : "=f"(y) : "f"(x)); return y;
}
__device__ __forceinline__ float sigf(float x) { return frcp(1.0f + fexp(-x)); }
__device__ __forceinline__ float tanhfast(float x) {
    return fmaf(2.0f, frcp(1.0f + fexp(-2.0f * x)), -1.0f);
}
__device__ __forceinline__ void mma_bf16(float* c, const unsigned* a, const unsigned* b) {
    asm("mma.sync.aligned.m16n8k16.row.col.f32.bf16.bf16.f32 "
        "{%0,%1,%2,%3},{%4,%5,%6,%7},{%8,%9},{%0,%1,%2,%3};"
        : "+f"(c[0]), "+f"(c[1]), "+f"(c[2]), "+f"(c[3])
        : "r"(a[0]), "r"(a[1]), "r"(a[2]), "r"(a[3]), "r"(b[0]), "r"(b[1]));
}
// A (m16k16 row-major [r][k]): a0=(q,k0) a1=(q+8,k0) a2=(q,k0+8) a3=(q+8,k0+8)
__device__ __forceinline__ void lda(const char* sm, unsigned base, int m, int kt,
                                    int qid, int rid, unsigned* a) {
    const int r0 = qid + 16 * m, k0 = kt * 16 + rid * 2;
    a[0] = lds32(sm, base, r0,     k0);
    a[1] = lds32(sm, base, r0 + 8, k0);
    a[2] = lds32(sm, base, r0,     k0 + 8);
    a[3] = lds32(sm, base, r0 + 8, k0 + 8);
}
// B (k16n8, weights stored [n][k]): b0=(n, k0..k0+1) b1=(n, k0+8..k0+9), n = tile + qid
__device__ __forceinline__ void ldb(const char* sm, unsigned base, int n, int kt,
                                    int rid, unsigned* b) {
    const int k0 = kt * 16 + rid * 2;
    b[0] = lds32(sm, base, n, k0);
    b[1] = lds32(sm, base, n, k0 + 8);
}

__global__ void __launch_bounds__(NTH, 1)
lstm_mma(const float* __restrict__ xg,
         const float* __restrict__ W1g, const float* __restrict__ U1g,
         const float* __restrict__ b1g, const float* __restrict__ W2g,
         const float* __restrict__ U2g, const float* __restrict__ b2g,
         const float* __restrict__ Wdg, const float* __restrict__ bdg,
         const float* __restrict__ Wog, const float* __restrict__ bog,
         float* __restrict__ outg)
{
    extern __shared__ __align__(16) char SM[];
    const int tid  = threadIdx.x;
    const int w    = tid >> 5;
    const int lane = tid & 31;
    const int qid  = lane >> 2;
    const int rid  = lane & 3;
    const int w8q  = w * 8 + qid;      // B-operand n index component
    const int uu0  = w * 8 + rid * 2;  // C-fragment unit pair
    const int bglob = blockIdx.x * BB;

    // ---------------- init: hi/lo weight split into smem ----------------
    for (int i = tid; i < 32 * 256; i += NTH) {            // W1 [k][j]
        int k = i >> 8, j = i & 255;
        float v = W1g[i], hf = bfv(v);
        unsigned off = swz((unsigned)(j * 128 + k * 2));
        *(__nv_bfloat16*)(SM + W1HI + off) = __float2bfloat16(hf);
        *(__nv_bfloat16*)(SM + W1LO + off) = __float2bfloat16(v - hf);
    }
    for (int i = tid; i < 64 * 256; i += NTH) {            // U1/W2/U2 lo parts
        int k = i >> 8, j = i & 255;
        unsigned off = swz((unsigned)(j * 128 + k * 2));
        float v = U1g[i];
        *(__nv_bfloat16*)(SM + U1LO + off) = __float2bfloat16(v - bfv(v));
        v = W2g[i];
        *(__nv_bfloat16*)(SM + W2LO + off) = __float2bfloat16(v - bfv(v));
        v = U2g[i];
        *(__nv_bfloat16*)(SM + U2LO + off) = __float2bfloat16(v - bfv(v));
    }
    for (int i = tid; i < 8192; i += NTH) ((unsigned*)(SM + H1HI))[i] = 0;  // h bufs
    {   // stage x(0) -> parity 0
        int row = tid >> 3, f4 = tid & 7;
        float4 v = *(const float4*)(xg + ((size_t)(bglob + row) * T_STEPS) * 32 + f4 * 4);
        float a0 = bfv(v.x), a1 = bfv(v.y), a2 = bfv(v.z), a3 = bfv(v.w);
        sts32(SM, XHI, row, f4 * 4,     pack2(a0, a1));
        sts32(SM, XHI, row, f4 * 4 + 2, pack2(a2, a3));
        sts32(SM, XLO, row, f4 * 4,     pack2(v.x - a0, v.y - a1));
        sts32(SM, XLO, row, f4 * 4 + 2, pack2(v.z - a2, v.w - a3));
    }

    // resident hi B-fragments for U1/W2/U2 (gathered from global, [k][n] layout)
    unsigned u1h[4][4][2], w2h[4][4][2], u2h[4][4][2];
#pragma unroll
    for (int kt = 0; kt < 4; kt++)
#pragma unroll
        for (int g = 0; g < 4; g++) {
            const int k0 = kt * 16 + rid * 2, n = g * 64 + w8q;
            u1h[kt][g][0] = pack2(bfv(U1g[k0 * 256 + n]),       bfv(U1g[(k0 + 1) * 256 + n]));
            u1h[kt][g][1] = pack2(bfv(U1g[(k0 + 8) * 256 + n]), bfv(U1g[(k0 + 9) * 256 + n]));
            w2h[kt][g][0] = pack2(bfv(W2g[k0 * 256 + n]),       bfv(W2g[(k0 + 1) * 256 + n]));
            w2h[kt][g][1] = pack2(bfv(W2g[(k0 + 8) * 256 + n]), bfv(W2g[(k0 + 9) * 256 + n]));
            u2h[kt][g][0] = pack2(bfv(U2g[k0 * 256 + n]),       bfv(U2g[(k0 + 1) * 256 + n]));
            u2h[kt][g][1] = pack2(bfv(U2g[(k0 + 8) * 256 + n]), bfv(U2g[(k0 + 9) * 256 + n]));
        }
    float bi1[4][2], bi2[4][2];
#pragma unroll
    for (int g = 0; g < 4; g++) {
        bi1[g][0] = b1g[g * 64 + uu0]; bi1[g][1] = b1g[g * 64 + uu0 + 1];
        bi2[g][0] = b2g[g * 64 + uu0]; bi2[g][1] = b2g[g * 64 + uu0 + 1];
    }
    float c1[8], c2[8];
#pragma unroll
    for (int i = 0; i < 8; i++) { c1[i] = 0.0f; c2[i] = 0.0f; }

    __syncthreads();

    for (int t = 0; t < T_STEPS; t++) {
        const int p = t & 1, q = p ^ 1;

        // ======== phase 1: z1 = x(t)@W1 + h1(t-1)@U1 + b1 ; update c1,h1 ========
        {
            float zc[4][8];
#pragma unroll
            for (int g = 0; g < 4; g++)
#pragma unroll
                for (int m = 0; m < 2; m++) {
                    zc[g][m * 4 + 0] = bi1[g][0]; zc[g][m * 4 + 1] = bi1[g][1];
                    zc[g][m * 4 + 2] = bi1[g][0]; zc[g][m * 4 + 3] = bi1[g][1];
                }
#pragma unroll
            for (int kt = 0; kt < 2; kt++) {               // x part, K=32
                unsigned bh[4][2], bl[4][2];
#pragma unroll
                for (int g = 0; g < 4; g++) {
                    ldb(SM, W1HI, g * 64 + w8q, kt, rid, bh[g]);
                    ldb(SM, W1LO, g * 64 + w8q, kt, rid, bl[g]);
                }
#pragma unroll
                for (int m = 0; m < 2; m++) {
                    unsigned ah[4], al[4];
                    lda(SM, XHI + p * 4096, m, kt, qid, rid, ah);
                    lda(SM, XLO + p * 4096, m, kt, qid, rid, al);
#pragma unroll
                    for (int g = 0; g < 4; g++) {
                        mma_bf16(zc[g] + m * 4, ah, bh[g]);
                        mma_bf16(zc[g] + m * 4, al, bh[g]);
                        mma_bf16(zc[g] + m * 4, ah, bl[g]);
                    }
                }
            }
#pragma unroll
            for (int kt = 0; kt < 4; kt++) {               // h1 part, K=64
                unsigned bl[4][2];
#pragma unroll
                for (int g = 0; g < 4; g++)
                    ldb(SM, U1LO, g * 64 + w8q, kt, rid, bl[g]);
#pragma unroll
                for (int m = 0; m < 2; m++) {
                    unsigned ah[4], al[4];
                    lda(SM, H1HI + q * 4096, m, kt, qid, rid, ah);
                    lda(SM, H1LO + q * 4096, m, kt, qid, rid, al);
#pragma unroll
                    for (int g = 0; g < 4; g++) {
                        mma_bf16(zc[g] + m * 4, ah, u1h[kt][g]);
                        mma_bf16(zc[g] + m * 4, al, u1h[kt][g]);
                        mma_bf16(zc[g] + m * 4, ah, bl[g]);
                    }
                }
            }
#pragma unroll
            for (int m = 0; m < 2; m++)
#pragma unroll
                for (int hh = 0; hh < 2; hh++) {
                    const int i0 = m * 4 + hh * 2;
                    const int r  = qid + 16 * m + 8 * hh;
                    float zi = zc[0][i0], zf = zc[1][i0], zg = zc[2][i0], zo = zc[3][i0];
                    c1[i0] = sigf(zf) * c1[i0] + sigf(zi) * tanhfast(zg);
                    float hv0 = sigf(zo) * tanhfast(c1[i0]);
                    zi = zc[0][i0+1]; zf = zc[1][i0+1]; zg = zc[2][i0+1]; zo = zc[3][i0+1];
                    c1[i0+1] = sigf(zf) * c1[i0+1] + sigf(zi) * tanhfast(zg);
                    float hv1 = sigf(zo) * tanhfast(c1[i0+1]);
                    float a0 = bfv(hv0), a1 = bfv(hv1);
                    sts32(SM, H1HI + p * 4096, r, uu0, pack2(a0, a1));
                    sts32(SM, H1LO + p * 4096, r, uu0, pack2(hv0 - a0, hv1 - a1));
                }
        }
        __syncthreads();

        // ======== phase 2: z2 = h1(t)@W2 + h2(t-1)@U2 + b2 ; update c2,h2 ========
        {
            if (t < T_STEPS - 1) {                         // stage x(t+1) -> parity q
                int row = tid >> 3, f4 = tid & 7;
                float4 v = *(const float4*)(xg + ((size_t)(bglob + row) * T_STEPS + t + 1) * 32 + f4 * 4);
                float a0 = bfv(v.x), a1 = bfv(v.y), a2 = bfv(v.z), a3 = bfv(v.w);
                sts32(SM, XHI + q * 4096, row, f4 * 4,     pack2(a0, a1));
                sts32(SM, XHI + q * 4096, row, f4 * 4 + 2, pack2(a2, a3));
                sts32(SM, XLO + q * 4096, row, f4 * 4,     pack2(v.x - a0, v.y - a1));
                sts32(SM, XLO + q * 4096, row, f4 * 4 + 2, pack2(v.z - a2, v.w - a3));
            }
            float zc[4][8];
#pragma unroll
            for (int g = 0; g < 4; g++)
#pragma unroll
                for (int m = 0; m < 2; m++) {
                    zc[g][m * 4 + 0] = bi2[g][0]; zc[g][m * 4 + 1] = bi2[g][1];
                    zc[g][m * 4 + 2] = bi2[g][0]; zc[g][m * 4 + 3] = bi2[g][1];
                }
#pragma unroll
            for (int kt = 0; kt < 4; kt++) {
                unsigned blw[4][2], blu[4][2];
#pragma unroll
                for (int g = 0; g < 4; g++) {
                    ldb(SM, W2LO, g * 64 + w8q, kt, rid, blw[g]);
                    ldb(SM, U2LO, g * 64 + w8q, kt, rid, blu[g]);
                }
#pragma unroll
                for (int m = 0; m < 2; m++) {
                    unsigned ah[4], al[4];
                    lda(SM, H1HI + p * 4096, m, kt, qid, rid, ah);
                    lda(SM, H1LO + p * 4096, m, kt, qid, rid, al);
#pragma unroll
                    for (int g = 0; g < 4; g++) {
                        mma_bf16(zc[g] + m * 4, ah, w2h[kt][g]);
                        mma_bf16(zc[g] + m * 4, al, w2h[kt][g]);
                        mma_bf16(zc[g] + m * 4, ah, blw[g]);
                    }
                    lda(SM, H2HI + q * 4096, m, kt, qid, rid, ah);
                    lda(SM, H2LO + q * 4096, m, kt, qid, rid, al);
#pragma unroll
                    for (int g = 0; g < 4; g++) {
                        mma_bf16(zc[g] + m * 4, ah, u2h[kt][g]);
                        mma_bf16(zc[g] + m * 4, al, u2h[kt][g]);
                        mma_bf16(zc[g] + m * 4, ah, blu[g]);
                    }
                }
            }
#pragma unroll
            for (int m = 0; m < 2; m++)
#pragma unroll
                for (int hh = 0; hh < 2; hh++) {
                    const int i0 = m * 4 + hh * 2;
                    const int r  = qid + 16 * m + 8 * hh;
                    float zi = zc[0][i0], zf = zc[1][i0], zg = zc[2][i0], zo = zc[3][i0];
                    c2[i0] = sigf(zf) * c2[i0] + sigf(zi) * tanhfast(zg);
                    float hv0 = sigf(zo) * tanhfast(c2[i0]);
                    zi = zc[0][i0+1]; zf = zc[1][i0+1]; zg = zc[2][i0+1]; zo = zc[3][i0+1];
                    c2[i0+1] = sigf(zf) * c2[i0+1] + sigf(zi) * tanhfast(zg);
                    float hv1 = sigf(zo) * tanhfast(c2[i0+1]);
                    float a0 = bfv(hv0), a1 = bfv(hv1);
                    sts32(SM, H2HI + p * 4096, r, uu0, pack2(a0, a1));
                    sts32(SM, H2LO + p * 4096, r, uu0, pack2(hv0 - a0, hv1 - a1));
                    if (t == T_STEPS - 1) {                // fp32 h2 for dense heads
                        float* dst = (float*)(SM + H2F) + r * 64 + uu0;
                        dst[0] = hv0; dst[1] = hv1;
                    }
                }
        }
        __syncthreads();
    }

    // ---------- dense head 1: d = sigmoid(h2 @ Wd + bd) -> fp32 scratch at H1HI ----------
    {
        const float* h2f = (const float*)(SM + H2F);
        float* ds = (float*)(SM + H1HI);
        const int uu = tid & 63, rg = tid >> 6;            // 4 groups x 8 rows
        const float bdv = bdg[uu];
#pragma unroll
        for (int r = 0; r < 8; r++) {
            int row = rg * 8 + r;
            float a = bdv;
#pragma unroll 8
            for (int k = 0; k < 64; k++)
                a += h2f[row * 64 + k] * Wdg[k * 64 + uu];
            ds[row * 64 + uu] = sigf(a);
        }
    }
    __syncthreads();
    // ---------- dense head 2: out = sigmoid(d @ Wo + bo), 8 warps x 4 rows ----------
    {
        const float* ds = (const float*)(SM + H1HI);
        const float bov = bog[0];
        const float wo0 = Wog[lane], wo1 = Wog[lane + 32];
#pragma unroll
        for (int r = 0; r < 4; r++) {
            int row = w * 4 + r;
            float pv = ds[row * 64 + lane] * wo0 + ds[row * 64 + lane + 32] * wo1;
#pragma unroll
            for (int s = 16; s; s >>= 1)
                pv += __shfl_xor_sync(0xffffffffu, pv, s);
            if (lane == 0)
                outg[bglob + row] = sigf(pv + bov);
        }
    }
}

extern "C" void kernel_launch(void* const* d_in, const int* in_sizes, int n_in,
                              void* d_out, int out_size)
{
    const float* x  = (const float*)d_in[0];
    const float* W1 = (const float*)d_in[1];
    const float* U1 = (const float*)d_in[2];
    const float* b1 = (const float*)d_in[3];
    const float* W2 = (const float*)d_in[4];
    const float* U2 = (const float*)d_in[5];
    const float* b2 = (const float*)d_in[6];
    const float* Wd = (const float*)d_in[7];
    const float* bd = (const float*)d_in[8];
    const float* Wo = (const float*)d_in[9];
    const float* bo = (const float*)d_in[10];
    float* out = (float*)d_out;

    cudaFuncSetAttribute(lstm_mma, cudaFuncAttributeMaxDynamicSharedMemorySize, SMEM_BYTES);
    lstm_mma<<<BATCH / BB, NTH, SMEM_BYTES>>>(x, W1, U1, b1, W2, U2, b2,
                                              Wd, bd, Wo, bo, out);
}

// round 14
// speedup vs baseline: 2.8038x; 1.1114x over previous
#include <cuda_runtime.h>
#include <cuda_bf16.h>

#define T_STEPS 256
#define BATCH   4096
#define BB      32
#define NTH     512
#define SMEM_BYTES 221184

// smem byte offsets (all regions 128B-row swizzled bf16 unless noted)
#define U1LO 0        // [256 n][64 k]
#define W2LO 32768
#define U2LO 65536
#define W1HI 98304    // [256 n][32 k]
#define W1LO 131072
#define H1HI 163840   // [2 parity][32 r][64 k] (4096 B per parity)
#define H1LO 172032
#define H2HI 180224
#define H2LO 188416
#define XHI  196608   // [2 parity][32 r][32 k]
#define XLO  204800
#define H2F  212992   // [32][64] fp32 final h2

__device__ __forceinline__ unsigned swz(unsigned off) { return off ^ ((off >> 3) & 0x70); }
__device__ __forceinline__ unsigned lds32(const char* sm, unsigned base, int r, int k) {
    return *(const unsigned*)(sm + base + swz((unsigned)(r * 128 + k * 2)));
}
__device__ __forceinline__ void sts32(char* sm, unsigned base, int r, int k, unsigned v) {
    *(unsigned*)(sm + base + swz((unsigned)(r * 128 + k * 2))) = v;
}
__device__ __forceinline__ unsigned pack2(float e0, float e1) {
    unsigned r;
    asm("cvt.rn.bf16x2.f32 %0, %1, %2;" : "=r"(r) : "f"(e1), "f"(e0));
    return r;
}
__device__ __forceinline__ float bfv(float v) { return __bfloat162float(__float2bfloat16(v)); }
__device__ __forceinline__ float fexp(float x) {
    float y; asm("ex2.approx.f32 %0, %1;" : "=f"(y) : "f"(x * 1.4426950408889634f)); return y;
}
__device__ __forceinline__ float frcp(float x) {
    float y; asm("rcp.approx.f32 %0, %1;" : "=f"(y) : "f"(x)); return y;
}
__device__ __forceinline__ float sigf(float x) { return frcp(1.0f + fexp(-x)); }
__device__ __forceinline__ float tanhfast(float x) {
    return fmaf(2.0f, frcp(1.0f + fexp(-2.0f * x)), -1.0f);
}
__device__ __forceinline__ void mma_bf16(float* c, const unsigned* a, const unsigned* b) {
    asm("mma.sync.aligned.m16n8k16.row.col.f32.bf16.bf16.f32 "
        "{%0,%1,%2,%3},{%4,%5,%6,%7},{%8,%9},{%0,%1,%2,%3};"
        : "+f"(c[0]), "+f"(c[1]), "+f"(c[2]), "+f"(c[3])
        : "r"(a[0]), "r"(a[1]), "r"(a[2]), "r"(a[3]), "r"(b[0]), "r"(b[1]));
}
__device__ __forceinline__ void lda(const char* sm, unsigned base, int m, int kt,
                                    int qid, int rid, unsigned* a) {
    const int r0 = qid + 16 * m, k0 = kt * 16 + rid * 2;
    a[0] = lds32(sm, base, r0,     k0);
    a[1] = lds32(sm, base, r0 + 8, k0);
    a[2] = lds32(sm, base, r0,     k0 + 8);
    a[3] = lds32(sm, base, r0 + 8, k0 + 8);
}
__device__ __forceinline__ void ldb(const char* sm, unsigned base, int n, int kt,
                                    int rid, unsigned* b) {
    const int k0 = kt * 16 + rid * 2;
    b[0] = lds32(sm, base, n, k0);
    b[1] = lds32(sm, base, n, k0 + 8);
}

__global__ void __launch_bounds__(NTH, 1)
lstm_mma(const float* __restrict__ xg,
         const float* __restrict__ W1g, const float* __restrict__ U1g,
         const float* __restrict__ b1g, const float* __restrict__ W2g,
         const float* __restrict__ U2g, const float* __restrict__ b2g,
         const float* __restrict__ Wdg, const float* __restrict__ bdg,
         const float* __restrict__ Wog, const float* __restrict__ bog,
         float* __restrict__ outg)
{
    extern __shared__ __align__(16) char SM[];
    const int tid  = threadIdx.x;
    const int w    = tid >> 5;
    const int lane = tid & 31;
    const int qid  = lane >> 2;
    const int rid  = lane & 3;
    const int grp  = w >> 3;          // 0 = layer1 warps, 1 = layer2 warps
    const int wl   = w & 7;           // warp index within group
    const int wg_tid = tid & 255;
    const int w8q  = wl * 8 + qid;
    const int uu0  = wl * 8 + rid * 2;
    const int bglob = blockIdx.x * BB;

    // ---------------- init: hi/lo weight split into smem ----------------
    for (int i = tid; i < 32 * 256; i += NTH) {            // W1 [k][j]
        int k = i >> 8, j = i & 255;
        float v = W1g[i], hf = bfv(v);
        unsigned off = swz((unsigned)(j * 128 + k * 2));
        *(__nv_bfloat16*)(SM + W1HI + off) = __float2bfloat16(hf);
        *(__nv_bfloat16*)(SM + W1LO + off) = __float2bfloat16(v - hf);
    }
    for (int i = tid; i < 64 * 256; i += NTH) {            // lo parts of U1/W2/U2
        int k = i >> 8, j = i & 255;
        unsigned off = swz((unsigned)(j * 128 + k * 2));
        float v = U1g[i];
        *(__nv_bfloat16*)(SM + U1LO + off) = __float2bfloat16(v - bfv(v));
        v = W2g[i];
        *(__nv_bfloat16*)(SM + W2LO + off) = __float2bfloat16(v - bfv(v));
        v = U2g[i];
        *(__nv_bfloat16*)(SM + U2LO + off) = __float2bfloat16(v - bfv(v));
    }
    for (int i = tid; i < 8192; i += NTH) ((unsigned*)(SM + H1HI))[i] = 0;
    if (tid < 256) {   // stage x(0) -> parity 0
        int row = tid >> 3, f4 = tid & 7;
        float4 v = *(const float4*)(xg + ((size_t)(bglob + row) * T_STEPS) * 32 + f4 * 4);
        float a0 = bfv(v.x), a1 = bfv(v.y), a2 = bfv(v.z), a3 = bfv(v.w);
        sts32(SM, XHI, row, f4 * 4,     pack2(a0, a1));
        sts32(SM, XHI, row, f4 * 4 + 2, pack2(a2, a3));
        sts32(SM, XLO, row, f4 * 4,     pack2(v.x - a0, v.y - a1));
        sts32(SM, XLO, row, f4 * 4 + 2, pack2(v.z - a2, v.w - a3));
    }

    // Overlaid resident hi B-fragments:
    //   grp 0: fA = U1 hi, fB[0..1] = W1 hi     grp 1: fA = W2 hi, fB = U2 hi
    unsigned fA[4][4][2], fB[4][4][2];
    float bi[4][2];
    {
        const float* Ma = (grp == 0) ? U1g : W2g;
        const float* Mb = (grp == 0) ? W1g : U2g;
        const int ktb = (grp == 0) ? 2 : 4;
#pragma unroll
        for (int kt = 0; kt < 4; kt++)
#pragma unroll
            for (int g = 0; g < 4; g++) {
                const int k0 = kt * 16 + rid * 2, n = g * 64 + w8q;
                fA[kt][g][0] = pack2(bfv(Ma[k0 * 256 + n]),       bfv(Ma[(k0 + 1) * 256 + n]));
                fA[kt][g][1] = pack2(bfv(Ma[(k0 + 8) * 256 + n]), bfv(Ma[(k0 + 9) * 256 + n]));
                if (kt < ktb) {
                    fB[kt][g][0] = pack2(bfv(Mb[k0 * 256 + n]),       bfv(Mb[(k0 + 1) * 256 + n]));
                    fB[kt][g][1] = pack2(bfv(Mb[(k0 + 8) * 256 + n]), bfv(Mb[(k0 + 9) * 256 + n]));
                }
            }
        const float* bg = (grp == 0) ? b1g : b2g;
#pragma unroll
        for (int g = 0; g < 4; g++) {
            bi[g][0] = bg[g * 64 + uu0]; bi[g][1] = bg[g * 64 + uu0 + 1];
        }
    }
    float cs[8];
#pragma unroll
    for (int i = 0; i < 8; i++) cs[i] = 0.0f;

    __syncthreads();

    for (int i = 0; i <= T_STEPS; i++) {
        const int p = i & 1, q = p ^ 1;

        if (grp == 0) {
            // =========== layer 1, step i: z1 = x(i)@W1 + h1(i-1)@U1 + b1 ===========
            if (i < T_STEPS) {
#pragma unroll
                for (int m = 0; m < 2; m++) {
                    float zc[4][4];
#pragma unroll
                    for (int g = 0; g < 4; g++) {
                        zc[g][0] = bi[g][0]; zc[g][1] = bi[g][1];
                        zc[g][2] = bi[g][0]; zc[g][3] = bi[g][1];
                    }
#pragma unroll
                    for (int kt = 0; kt < 2; kt++) {        // x part (K=32)
                        unsigned bl[4][2], ah[4], al[4];
#pragma unroll
                        for (int g = 0; g < 4; g++) ldb(SM, W1LO, g * 64 + w8q, kt, rid, bl[g]);
                        lda(SM, XHI + p * 4096, m, kt, qid, rid, ah);
                        lda(SM, XLO + p * 4096, m, kt, qid, rid, al);
#pragma unroll
                        for (int g = 0; g < 4; g++) {
                            mma_bf16(zc[g], ah, fB[kt][g]);
                            mma_bf16(zc[g], al, fB[kt][g]);
                            mma_bf16(zc[g], ah, bl[g]);
                        }
                    }
#pragma unroll
                    for (int kt = 0; kt < 4; kt++) {        // h1 part (K=64)
                        unsigned bl[4][2], ah[4], al[4];
#pragma unroll
                        for (int g = 0; g < 4; g++) ldb(SM, U1LO, g * 64 + w8q, kt, rid, bl[g]);
                        lda(SM, H1HI + q * 4096, m, kt, qid, rid, ah);
                        lda(SM, H1LO + q * 4096, m, kt, qid, rid, al);
#pragma unroll
                        for (int g = 0; g < 4; g++) {
                            mma_bf16(zc[g], ah, fA[kt][g]);
                            mma_bf16(zc[g], al, fA[kt][g]);
                            mma_bf16(zc[g], ah, bl[g]);
                        }
                    }
#pragma unroll
                    for (int hh = 0; hh < 2; hh++) {
                        const int i0 = hh * 2, ci = m * 4 + hh * 2;
                        const int r  = qid + 16 * m + 8 * hh;
                        float zi = zc[0][i0], zf = zc[1][i0], zg = zc[2][i0], zo = zc[3][i0];
                        cs[ci] = sigf(zf) * cs[ci] + sigf(zi) * tanhfast(zg);
                        float hv0 = sigf(zo) * tanhfast(cs[ci]);
                        zi = zc[0][i0+1]; zf = zc[1][i0+1]; zg = zc[2][i0+1]; zo = zc[3][i0+1];
                        cs[ci+1] = sigf(zf) * cs[ci+1] + sigf(zi) * tanhfast(zg);
                        float hv1 = sigf(zo) * tanhfast(cs[ci+1]);
                        float a0 = bfv(hv0), a1 = bfv(hv1);
                        sts32(SM, H1HI + p * 4096, r, uu0, pack2(a0, a1));
                        sts32(SM, H1LO + p * 4096, r, uu0, pack2(hv0 - a0, hv1 - a1));
                    }
                }
            }
        } else {
            // =========== layer 2, step i-1: z2 = h1(i-1)@W2 + h2(i-2)@U2 + b2 ===========
            if (i < T_STEPS - 1) {      // stage x(i+1) -> parity q (A reads it next iter)
                int row = wg_tid >> 3, f4 = wg_tid & 7;
                float4 v = *(const float4*)(xg + ((size_t)(bglob + row) * T_STEPS + i + 1) * 32 + f4 * 4);
                float a0 = bfv(v.x), a1 = bfv(v.y), a2 = bfv(v.z), a3 = bfv(v.w);
                sts32(SM, XHI + q * 4096, row, f4 * 4,     pack2(a0, a1));
                sts32(SM, XHI + q * 4096, row, f4 * 4 + 2, pack2(a2, a3));
                sts32(SM, XLO + q * 4096, row, f4 * 4,     pack2(v.x - a0, v.y - a1));
                sts32(SM, XLO + q * 4096, row, f4 * 4 + 2, pack2(v.z - a2, v.w - a3));
            }
            if (i >= 1) {
#pragma unroll
                for (int m = 0; m < 2; m++) {
                    float zc[4][4];
#pragma unroll
                    for (int g = 0; g < 4; g++) {
                        zc[g][0] = bi[g][0]; zc[g][1] = bi[g][1];
                        zc[g][2] = bi[g][0]; zc[g][3] = bi[g][1];
                    }
#pragma unroll
                    for (int kt = 0; kt < 4; kt++) {
                        unsigned blw[4][2], blu[4][2], ah[4], al[4];
#pragma unroll
                        for (int g = 0; g < 4; g++) {
                            ldb(SM, W2LO, g * 64 + w8q, kt, rid, blw[g]);
                            ldb(SM, U2LO, g * 64 + w8q, kt, rid, blu[g]);
                        }
                        lda(SM, H1HI + q * 4096, m, kt, qid, rid, ah);
                        lda(SM, H1LO + q * 4096, m, kt, qid, rid, al);
#pragma unroll
                        for (int g = 0; g < 4; g++) {
                            mma_bf16(zc[g], ah, fA[kt][g]);
                            mma_bf16(zc[g], al, fA[kt][g]);
                            mma_bf16(zc[g], ah, blw[g]);
                        }
                        lda(SM, H2HI + p * 4096, m, kt, qid, rid, ah);
                        lda(SM, H2LO + p * 4096, m, kt, qid, rid, al);
#pragma unroll
                        for (int g = 0; g < 4; g++) {
                            mma_bf16(zc[g], ah, fB[kt][g]);
                            mma_bf16(zc[g], al, fB[kt][g]);
                            mma_bf16(zc[g], ah, blu[g]);
                        }
                    }
#pragma unroll
                    for (int hh = 0; hh < 2; hh++) {
                        const int i0 = hh * 2, ci = m * 4 + hh * 2;
                        const int r  = qid + 16 * m + 8 * hh;
                        float zi = zc[0][i0], zf = zc[1][i0], zg = zc[2][i0], zo = zc[3][i0];
                        cs[ci] = sigf(zf) * cs[ci] + sigf(zi) * tanhfast(zg);
                        float hv0 = sigf(zo) * tanhfast(cs[ci]);
                        zi = zc[0][i0+1]; zf = zc[1][i0+1]; zg = zc[2][i0+1]; zo = zc[3][i0+1];
                        cs[ci+1] = sigf(zf) * cs[ci+1] + sigf(zi) * tanhfast(zg);
                        float hv1 = sigf(zo) * tanhfast(cs[ci+1]);
                        float a0 = bfv(hv0), a1 = bfv(hv1);
                        sts32(SM, H2HI + q * 4096, r, uu0, pack2(a0, a1));
                        sts32(SM, H2LO + q * 4096, r, uu0, pack2(hv0 - a0, hv1 - a1));
                        if (i == T_STEPS) {
                            float* dst = (float*)(SM + H2F) + r * 64 + uu0;
                            dst[0] = hv0; dst[1] = hv1;
                        }
                    }
                }
            }
        }
        __syncthreads();
    }

    // ---------- dense head 1: d = sigmoid(h2 @ Wd + bd) -> fp32 scratch at H1HI ----------
    {
        const float* h2f = (const float*)(SM + H2F);
        float* ds = (float*)(SM + H1HI);
        const int uu = tid & 63, rg = tid >> 6;            // 8 groups x 4 rows
        const float bdv = bdg[uu];
#pragma unroll
        for (int r = 0; r < 4; r++) {
            int row = rg * 4 + r;
            float a = bdv;
#pragma unroll 8
            for (int k = 0; k < 64; k++)
                a += h2f[row * 64 + k] * Wdg[k * 64 + uu];
            ds[row * 64 + uu] = sigf(a);
        }
    }
    __syncthreads();
    // ---------- dense head 2: out = sigmoid(d @ Wo + bo), 16 warps x 2 rows ----------
    {
        const float* ds = (const float*)(SM + H1HI);
        const float bov = bog[0];
        const float wo0 = Wog[lane], wo1 = Wog[lane + 32];
#pragma unroll
        for (int r = 0; r < 2; r++) {
            int row = w * 2 + r;
            float pv = ds[row * 64 + lane] * wo0 + ds[row * 64 + lane + 32] * wo1;
#pragma unroll
            for (int s = 16; s; s >>= 1)
                pv += __shfl_xor_sync(0xffffffffu, pv, s);
            if (lane == 0)
                outg[bglob + row] = sigf(pv + bov);
        }
    }
}

extern "C" void kernel_launch(void* const* d_in, const int* in_sizes, int n_in,
                              void* d_out, int out_size)
{
    const float* x  = (const float*)d_in[0];
    const float* W1 = (const float*)d_in[1];
    const float* U1 = (const float*)d_in[2];
    const float* b1 = (const float*)d_in[3];
    const float* W2 = (const float*)d_in[4];
    const float* U2 = (const float*)d_in[5];
    const float* b2 = (const float*)d_in[6];
    const float* Wd = (const float*)d_in[7];
    const float* bd = (const float*)d_in[8];
    const float* Wo = (const float*)d_in[9];
    const float* bo = (const float*)d_in[10];
    float* out = (float*)d_out;

    cudaFuncSetAttribute(lstm_mma, cudaFuncAttributeMaxDynamicSharedMemorySize, SMEM_BYTES);
    lstm_mma<<<BATCH / BB, NTH, SMEM_BYTES>>>(x, W1, U1, b1, W2, U2, b2,
                                              Wd, bd, Wo, bo, out);
}

// round 15
// speedup vs baseline: 3.2926x; 1.1744x over previous
#include <cuda_runtime.h>
#include <cuda_bf16.h>

#define T_STEPS 256
#define BATCH   4096
#define BB      32
#define NTH     512
#define SMEM_BYTES 221184

// smem regions (bf16, 128B rows, swizzle: byte (r,k2) at r*128 + (k2 ^ ((r&7)*16)))
#define U1LO 0
#define W2LO 32768
#define U2LO 65536
#define W1HI 98304
#define W1LO 131072
#define H1HI 163840   // [2 parity][32 r][64 k]
#define H1LO 172032
#define H2HI 180224
#define H2LO 188416
#define XHI  196608   // [2 parity][32 r][32 k]
#define XLO  204800
#define H2F  212992   // [32][64] fp32

__device__ __forceinline__ unsigned swz(unsigned off) { return off ^ ((off >> 3) & 0x70); }
__device__ __forceinline__ void sts32(char* sm, unsigned base, int r, int k, unsigned v) {
    *(unsigned*)(sm + base + swz((unsigned)(r * 128 + k * 2))) = v;
}
__device__ __forceinline__ unsigned pack2(float e0, float e1) {
    unsigned r;
    asm("cvt.rn.bf16x2.f32 %0, %1, %2;" : "=r"(r) : "f"(e1), "f"(e0));
    return r;
}
__device__ __forceinline__ float bfv(float v) { return __bfloat162float(__float2bfloat16(v)); }
__device__ __forceinline__ float fexp(float x) {
    float y; asm("ex2.approx.f32 %0, %1;" : "=f"(y) : "f"(x * 1.4426950408889634f)); return y;
}
__device__ __forceinline__ float frcp(float x) {
    float y; asm("rcp.approx.f32 %0, %1;" : "=f"(y) : "f"(x)); return y;
}
__device__ __forceinline__ float sigf(float x) { return frcp(1.0f + fexp(-x)); }
__device__ __forceinline__ float tanhfast(float x) {
    return fmaf(2.0f, frcp(1.0f + fexp(-2.0f * x)), -1.0f);
}
__device__ __forceinline__ void mma_bf16(float* c, const unsigned* a, const unsigned* b) {
    asm volatile("mma.sync.aligned.m16n8k16.row.col.f32.bf16.bf16.f32 "
        "{%0,%1,%2,%3},{%4,%5,%6,%7},{%8,%9},{%0,%1,%2,%3};"
        : "+f"(c[0]), "+f"(c[1]), "+f"(c[2]), "+f"(c[3])
        : "r"(a[0]), "r"(a[1]), "r"(a[2]), "r"(a[3]), "r"(b[0]), "r"(b[1]));
}
// 32-bit shared-window accesses with precomputed bases (+compile-time imms)
__device__ __forceinline__ unsigned ldsw(unsigned a) {
    unsigned v; asm volatile("ld.shared.b32 %0, [%1];" : "=r"(v) : "r"(a)); return v;
}
__device__ __forceinline__ void stsw(unsigned a, unsigned v) {
    asm volatile("st.shared.b32 [%0], %1;" :: "r"(a), "r"(v));
}
__device__ __forceinline__ void ldaF(const unsigned* ab, int kt, int imm, unsigned* a) {
    a[0] = ldsw(ab[kt * 2]     + imm);
    a[1] = ldsw(ab[kt * 2]     + imm + 1024);
    a[2] = ldsw(ab[kt * 2 + 1] + imm);
    a[3] = ldsw(ab[kt * 2 + 1] + imm + 1024);
}
__device__ __forceinline__ void ldbF(const unsigned* ab, unsigned wlq, int kt, int imm, unsigned* b) {
    b[0] = ldsw(ab[kt * 2]     + wlq + imm);
    b[1] = ldsw(ab[kt * 2 + 1] + wlq + imm);
}

// ---------------- layer 1 step (group A), parity P ----------------
template<int P>
__device__ __forceinline__ void layer1_step(
    const unsigned* ab, unsigned wlq, unsigned hsb,
    const unsigned (*fU1)[4][2], const unsigned (*fW1)[4][2],
    const float (*bi)[2], float* cs)
{
    constexpr int Q = P ^ 1;
#pragma unroll
    for (int m = 0; m < 2; m++) {
        float zc[4][4];
#pragma unroll
        for (int g = 0; g < 4; g++) {
            zc[g][0] = bi[g][0]; zc[g][1] = bi[g][1];
            zc[g][2] = bi[g][0]; zc[g][3] = bi[g][1];
        }
#pragma unroll
        for (int kt = 0; kt < 2; kt++) {            // x part (K=32)
            unsigned ah[4], al[4];
            ldaF(ab, kt, XHI + P * 4096 + m * 2048, ah);
            ldaF(ab, kt, XLO + P * 4096 + m * 2048, al);
#pragma unroll
            for (int g = 0; g < 4; g++) {
                unsigned bl[2];
                ldbF(ab, wlq, kt, W1LO + g * 8192, bl);
                mma_bf16(zc[g], ah, fW1[kt][g]);
                mma_bf16(zc[g], al, fW1[kt][g]);
                mma_bf16(zc[g], ah, bl);
            }
        }
#pragma unroll
        for (int kt = 0; kt < 4; kt++) {            // h1 part (K=64)
            unsigned ah[4], al[4];
            ldaF(ab, kt, H1HI + Q * 4096 + m * 2048, ah);
            ldaF(ab, kt, H1LO + Q * 4096 + m * 2048, al);
#pragma unroll
            for (int g = 0; g < 4; g++) {
                unsigned bl[2];
                ldbF(ab, wlq, kt, U1LO + g * 8192, bl);
                mma_bf16(zc[g], ah, fU1[kt][g]);
                mma_bf16(zc[g], al, fU1[kt][g]);
                mma_bf16(zc[g], ah, bl);
            }
        }
#pragma unroll
        for (int hh = 0; hh < 2; hh++) {
            const int ci = m * 4 + hh * 2;
            float zi = zc[0][hh*2], zf = zc[1][hh*2], zg = zc[2][hh*2], zo = zc[3][hh*2];
            cs[ci] = sigf(zf) * cs[ci] + sigf(zi) * tanhfast(zg);
            float hv0 = sigf(zo) * tanhfast(cs[ci]);
            zi = zc[0][hh*2+1]; zf = zc[1][hh*2+1]; zg = zc[2][hh*2+1]; zo = zc[3][hh*2+1];
            cs[ci+1] = sigf(zf) * cs[ci+1] + sigf(zi) * tanhfast(zg);
            float hv1 = sigf(zo) * tanhfast(cs[ci+1]);
            float a0 = bfv(hv0), a1 = bfv(hv1);
            stsw(hsb + (H1HI + P * 4096 + m * 2048 + hh * 1024), pack2(a0, a1));
            stsw(hsb + (H1LO + P * 4096 + m * 2048 + hh * 1024), pack2(hv0 - a0, hv1 - a1));
        }
    }
}

// ---------------- layer 2 step (group B), parity P ----------------
// reads h1[Q], h2[P]; writes h2[Q]; FIN: also fp32 h2 to H2F
template<int P, bool FIN>
__device__ __forceinline__ void layer2_step(
    char* SM, const unsigned* ab, unsigned wlq, unsigned hsb,
    const unsigned (*fW2)[4][2], const unsigned (*fU2)[4][2],
    const float (*bi)[2], float* cs, int qid, int uu0)
{
    constexpr int Q = P ^ 1;
#pragma unroll
    for (int m = 0; m < 2; m++) {
        float zc[4][4];
#pragma unroll
        for (int g = 0; g < 4; g++) {
            zc[g][0] = bi[g][0]; zc[g][1] = bi[g][1];
            zc[g][2] = bi[g][0]; zc[g][3] = bi[g][1];
        }
#pragma unroll
        for (int kt = 0; kt < 4; kt++) {
            unsigned ah[4], al[4];
            ldaF(ab, kt, H1HI + Q * 4096 + m * 2048, ah);
            ldaF(ab, kt, H1LO + Q * 4096 + m * 2048, al);
#pragma unroll
            for (int g = 0; g < 4; g++) {
                unsigned bl[2];
                ldbF(ab, wlq, kt, W2LO + g * 8192, bl);
                mma_bf16(zc[g], ah, fW2[kt][g]);
                mma_bf16(zc[g], al, fW2[kt][g]);
                mma_bf16(zc[g], ah, bl);
            }
            ldaF(ab, kt, H2HI + P * 4096 + m * 2048, ah);
            ldaF(ab, kt, H2LO + P * 4096 + m * 2048, al);
#pragma unroll
            for (int g = 0; g < 4; g++) {
                unsigned bl[2];
                ldbF(ab, wlq, kt, U2LO + g * 8192, bl);
                mma_bf16(zc[g], ah, fU2[kt][g]);
                mma_bf16(zc[g], al, fU2[kt][g]);
                mma_bf16(zc[g], ah, bl);
            }
        }
#pragma unroll
        for (int hh = 0; hh < 2; hh++) {
            const int ci = m * 4 + hh * 2;
            float zi = zc[0][hh*2], zf = zc[1][hh*2], zg = zc[2][hh*2], zo = zc[3][hh*2];
            cs[ci] = sigf(zf) * cs[ci] + sigf(zi) * tanhfast(zg);
            float hv0 = sigf(zo) * tanhfast(cs[ci]);
            zi = zc[0][hh*2+1]; zf = zc[1][hh*2+1]; zg = zc[2][hh*2+1]; zo = zc[3][hh*2+1];
            cs[ci+1] = sigf(zf) * cs[ci+1] + sigf(zi) * tanhfast(zg);
            float hv1 = sigf(zo) * tanhfast(cs[ci+1]);
            float a0 = bfv(hv0), a1 = bfv(hv1);
            stsw(hsb + (H2HI + Q * 4096 + m * 2048 + hh * 1024), pack2(a0, a1));
            stsw(hsb + (H2LO + Q * 4096 + m * 2048 + hh * 1024), pack2(hv0 - a0, hv1 - a1));
            if (FIN) {
                const int r = qid + 16 * m + 8 * hh;
                float* dst = (float*)(SM + H2F) + r * 64 + uu0;
                dst[0] = hv0; dst[1] = hv1;
            }
        }
    }
}

// stage x(t) into parity DP (group A, 256 threads)
template<int DP>
__device__ __forceinline__ void stage_x(char* SM, const float* xg, int bglob, int wg_tid, int t)
{
    int row = wg_tid >> 3, f4 = wg_tid & 7;
    float4 v = *(const float4*)(xg + ((size_t)(bglob + row) * T_STEPS + t) * 32 + f4 * 4);
    float a0 = bfv(v.x), a1 = bfv(v.y), a2 = bfv(v.z), a3 = bfv(v.w);
    sts32(SM, XHI + DP * 4096, row, f4 * 4,     pack2(a0, a1));
    sts32(SM, XHI + DP * 4096, row, f4 * 4 + 2, pack2(a2, a3));
    sts32(SM, XLO + DP * 4096, row, f4 * 4,     pack2(v.x - a0, v.y - a1));
    sts32(SM, XLO + DP * 4096, row, f4 * 4 + 2, pack2(v.z - a2, v.w - a3));
}

__global__ void __launch_bounds__(NTH, 1)
lstm_mma(const float* __restrict__ xg,
         const float* __restrict__ W1g, const float* __restrict__ U1g,
         const float* __restrict__ b1g, const float* __restrict__ W2g,
         const float* __restrict__ U2g, const float* __restrict__ b2g,
         const float* __restrict__ Wdg, const float* __restrict__ bdg,
         const float* __restrict__ Wog, const float* __restrict__ bog,
         float* __restrict__ outg)
{
    extern __shared__ __align__(16) char SM[];
    const int tid  = threadIdx.x;
    const int w    = tid >> 5;
    const int lane = tid & 31;
    const int qid  = lane >> 2;
    const int rid  = lane & 3;
    const int grp  = w >> 3;
    const int wl   = w & 7;
    const int wg_tid = tid & 255;
    const int w8q  = wl * 8 + qid;
    const int uu0  = wl * 8 + rid * 2;
    const int bglob = blockIdx.x * BB;

    // ---------------- init: hi/lo weight split ----------------
    for (int i = tid; i < 32 * 256; i += NTH) {
        int k = i >> 8, j = i & 255;
        float v = W1g[i], hf = bfv(v);
        unsigned off = swz((unsigned)(j * 128 + k * 2));
        *(__nv_bfloat16*)(SM + W1HI + off) = __float2bfloat16(hf);
        *(__nv_bfloat16*)(SM + W1LO + off) = __float2bfloat16(v - hf);
    }
    for (int i = tid; i < 64 * 256; i += NTH) {
        int k = i >> 8, j = i & 255;
        unsigned off = swz((unsigned)(j * 128 + k * 2));
        float v = U1g[i];
        *(__nv_bfloat16*)(SM + U1LO + off) = __float2bfloat16(v - bfv(v));
        v = W2g[i];
        *(__nv_bfloat16*)(SM + W2LO + off) = __float2bfloat16(v - bfv(v));
        v = U2g[i];
        *(__nv_bfloat16*)(SM + U2LO + off) = __float2bfloat16(v - bfv(v));
    }
    for (int i = tid; i < 8192; i += NTH) ((unsigned*)(SM + H1HI))[i] = 0;
    if (tid < 256) stage_x<0>(SM, xg, bglob, tid, 0);

    // resident hi fragments: grp0 fA=U1, fB=W1(kt<2); grp1 fA=W2, fB=U2
    unsigned fA[4][4][2], fB[4][4][2];
    float bi[4][2];
    {
        const float* Ma = (grp == 0) ? U1g : W2g;
        const float* Mb = (grp == 0) ? W1g : U2g;
        const int ktb = (grp == 0) ? 2 : 4;
#pragma unroll
        for (int kt = 0; kt < 4; kt++)
#pragma unroll
            for (int g = 0; g < 4; g++) {
                const int k0 = kt * 16 + rid * 2, n = g * 64 + w8q;
                fA[kt][g][0] = pack2(bfv(Ma[k0 * 256 + n]),       bfv(Ma[(k0 + 1) * 256 + n]));
                fA[kt][g][1] = pack2(bfv(Ma[(k0 + 8) * 256 + n]), bfv(Ma[(k0 + 9) * 256 + n]));
                if (kt < ktb) {
                    fB[kt][g][0] = pack2(bfv(Mb[k0 * 256 + n]),       bfv(Mb[(k0 + 1) * 256 + n]));
                    fB[kt][g][1] = pack2(bfv(Mb[(k0 + 8) * 256 + n]), bfv(Mb[(k0 + 9) * 256 + n]));
                }
            }
        const float* bgp = (grp == 0) ? b1g : b2g;
#pragma unroll
        for (int g = 0; g < 4; g++) {
            bi[g][0] = bgp[g * 64 + uu0]; bi[g][1] = bgp[g * 64 + uu0 + 1];
        }
    }

    // precomputed 32-bit shared bases (loop-invariant; imms added at use sites)
    const unsigned smb = (unsigned)__cvta_generic_to_shared(SM);
    unsigned ab[8];
#pragma unroll
    for (int kt = 0; kt < 4; kt++)
#pragma unroll
        for (int o = 0; o < 2; o++)
            ab[kt * 2 + o] = smb + qid * 128 + rid * 4 + (((unsigned)(kt * 32 + o * 16)) ^ (qid * 16));
    const unsigned wlq = wl * 1024;
    const unsigned hsb = smb + qid * 128 + rid * 4 + (((unsigned)(wl * 16)) ^ (qid * 16));

    float cs[8];
#pragma unroll
    for (int i = 0; i < 8; i++) cs[i] = 0.0f;

    __syncthreads();

    for (int it = 0; it < T_STEPS / 2; it++) {
        const int i0 = 2 * it;
        // ---- iteration i0 (P=0): A computes layer1(i0) + stages x(i0+1); B layer2(i0-1)
        if (grp == 0) {
            stage_x<1>(SM, xg, bglob, wg_tid, i0 + 1);
            layer1_step<0>(ab, wlq, hsb,
                           (const unsigned(*)[4][2])fA, (const unsigned(*)[4][2])fB,
                           (const float(*)[2])bi, cs);
        } else if (it > 0) {
            layer2_step<0, false>(SM, ab, wlq, hsb,
                                  (const unsigned(*)[4][2])fA, (const unsigned(*)[4][2])fB,
                                  (const float(*)[2])bi, cs, qid, uu0);
        }
        __syncthreads();
        // ---- iteration i0+1 (P=1): A layer1(i0+1) + stages x(i0+2); B layer2(i0)
        if (grp == 0) {
            if (it < T_STEPS / 2 - 1)
                stage_x<0>(SM, xg, bglob, wg_tid, i0 + 2);
            layer1_step<1>(ab, wlq, hsb,
                           (const unsigned(*)[4][2])fA, (const unsigned(*)[4][2])fB,
                           (const float(*)[2])bi, cs);
        } else {
            layer2_step<1, false>(SM, ab, wlq, hsb,
                                  (const unsigned(*)[4][2])fA, (const unsigned(*)[4][2])fB,
                                  (const float(*)[2])bi, cs, qid, uu0);
        }
        __syncthreads();
    }
    // tail: i=256 (P=0), B computes layer2(255) + fp32 store
    if (grp == 1)
        layer2_step<0, true>(SM, ab, wlq, hsb,
                             (const unsigned(*)[4][2])fA, (const unsigned(*)[4][2])fB,
                             (const float(*)[2])bi, cs, qid, uu0);
    __syncthreads();

    // ---------- dense head 1: d = sigmoid(h2 @ Wd + bd) -> fp32 scratch at H1HI ----------
    {
        const float* h2f = (const float*)(SM + H2F);
        float* ds = (float*)(SM + H1HI);
        const int uu = tid & 63, rg = tid >> 6;
        const float bdv = bdg[uu];
#pragma unroll
        for (int r = 0; r < 4; r++) {
            int row = rg * 4 + r;
            float a = bdv;
#pragma unroll 8
            for (int k = 0; k < 64; k++)
                a += h2f[row * 64 + k] * Wdg[k * 64 + uu];
            ds[row * 64 + uu] = sigf(a);
        }
    }
    __syncthreads();
    // ---------- dense head 2: out = sigmoid(d @ Wo + bo) ----------
    {
        const float* ds = (const float*)(SM + H1HI);
        const float bov = bog[0];
        const float wo0 = Wog[lane], wo1 = Wog[lane + 32];
#pragma unroll
        for (int r = 0; r < 2; r++) {
            int row = w * 2 + r;
            float pv = ds[row * 64 + lane] * wo0 + ds[row * 64 + lane + 32] * wo1;
#pragma unroll
            for (int s = 16; s; s >>= 1)
                pv += __shfl_xor_sync(0xffffffffu, pv, s);
            if (lane == 0)
                outg[bglob + row] = sigf(pv + bov);
        }
    }
}

extern "C" void kernel_launch(void* const* d_in, const int* in_sizes, int n_in,
                              void* d_out, int out_size)
{
    const float* x  = (const float*)d_in[0];
    const float* W1 = (const float*)d_in[1];
    const float* U1 = (const float*)d_in[2];
    const float* b1 = (const float*)d_in[3];
    const float* W2 = (const float*)d_in[4];
    const float* U2 = (const float*)d_in[5];
    const float* b2 = (const float*)d_in[6];
    const float* Wd = (const float*)d_in[7];
    const float* bd = (const float*)d_in[8];
    const float* Wo = (const float*)d_in[9];
    const float* bo = (const float*)d_in[10];
    float* out = (float*)d_out;

    cudaFuncSetAttribute(lstm_mma, cudaFuncAttributeMaxDynamicSharedMemorySize, SMEM_BYTES);
    lstm_mma<<<BATCH / BB, NTH, SMEM_BYTES>>>(x, W1, U1, b1, W2, U2, b2,
                                              Wd, bd, Wo, bo, out);
}

// round 17
// speedup vs baseline: 3.9577x; 1.2020x over previous
#include <cuda_runtime.h>
#include <cuda_bf16.h>

#define T_STEPS 256
#define BATCH   4096
#define BB      32
#define NTH     512
#define SMEM_BYTES 221184

// smem regions (bf16, 128B rows, swizzle: byte (r,k2) at r*128 + (k2 ^ ((r&7)*16)))
#define U1LO 0
#define W2LO 32768
#define U2LO 65536
#define W1HI 98304
#define W1LO 131072
#define H1HI 163840   // [2 parity][32 r][64 k]
#define H1LO 172032
#define H2HI 180224
#define H2LO 188416
#define XHI  196608   // [2 parity][32 r][32 k]
#define XLO  204800
#define H2F  212992   // [32][64] fp32

__device__ __forceinline__ unsigned swz(unsigned off) { return off ^ ((off >> 3) & 0x70); }
__device__ __forceinline__ void sts32(char* sm, unsigned base, int r, int k, unsigned v) {
    *(unsigned*)(sm + base + swz((unsigned)(r * 128 + k * 2))) = v;
}
__device__ __forceinline__ unsigned pack2(float e0, float e1) {
    unsigned r;
    asm("cvt.rn.bf16x2.f32 %0, %1, %2;" : "=r"(r) : "f"(e1), "f"(e0));
    return r;
}
__device__ __forceinline__ float bfv(float v) { return __bfloat162float(__float2bfloat16(v)); }
// HW tanh: single MUFU op on sm_75+
__device__ __forceinline__ float tanha(float x) {
    float y; asm("tanh.approx.f32 %0, %1;" : "=f"(y) : "f"(x)); return y;
}
__device__ __forceinline__ float sigf(float x) {
    return fmaf(0.5f, tanha(0.5f * x), 0.5f);
}
__device__ __forceinline__ float fexp(float x) {   // init/heads only
    float y; asm("ex2.approx.f32 %0, %1;" : "=f"(y) : "f"(x * 1.4426950408889634f)); return y;
}
__device__ __forceinline__ float frcp(float x) {
    float y; asm("rcp.approx.f32 %0, %1;" : "=f"(y) : "f"(x)); return y;
}
__device__ __forceinline__ void mma_bf16(float* c, const unsigned* a, const unsigned* b) {
    asm volatile("mma.sync.aligned.m16n8k16.row.col.f32.bf16.bf16.f32 "
        "{%0,%1,%2,%3},{%4,%5,%6,%7},{%8,%9},{%0,%1,%2,%3};"
        : "+f"(c[0]), "+f"(c[1]), "+f"(c[2]), "+f"(c[3])
        : "r"(a[0]), "r"(a[1]), "r"(a[2]), "r"(a[3]), "r"(b[0]), "r"(b[1]));
}
__device__ __forceinline__ unsigned ldsw(unsigned a) {
    unsigned v; asm volatile("ld.shared.b32 %0, [%1];" : "=r"(v) : "r"(a)); return v;
}
__device__ __forceinline__ void stsw(unsigned a, unsigned v) {
    asm volatile("st.shared.b32 [%0], %1;" :: "r"(a), "r"(v));
}
__device__ __forceinline__ void ldaF(const unsigned* ab, int kt, int imm, unsigned* a) {
    a[0] = ldsw(ab[kt * 2]     + imm);
    a[1] = ldsw(ab[kt * 2]     + imm + 1024);
    a[2] = ldsw(ab[kt * 2 + 1] + imm);
    a[3] = ldsw(ab[kt * 2 + 1] + imm + 1024);
}
__device__ __forceinline__ void ldbF(const unsigned* ab, unsigned wlq, int kt, int imm, unsigned* b) {
    b[0] = ldsw(ab[kt * 2]     + wlq + imm);
    b[1] = ldsw(ab[kt * 2 + 1] + wlq + imm);
}

// ---------------- layer 1 step (group A), parity P ----------------
template<int P>
__device__ __forceinline__ void layer1_step(
    const unsigned* ab, unsigned wlq, unsigned hsb,
    const unsigned (*fU1)[4][2], const unsigned (*fW1)[4][2],
    const float (*bi)[2], float* cs)
{
    constexpr int Q = P ^ 1;
#pragma unroll
    for (int m = 0; m < 2; m++) {
        float zc[4][4];
#pragma unroll
        for (int g = 0; g < 4; g++) {
            zc[g][0] = bi[g][0]; zc[g][1] = bi[g][1];
            zc[g][2] = bi[g][0]; zc[g][3] = bi[g][1];
        }
#pragma unroll
        for (int kt = 0; kt < 2; kt++) {            // x part (K=32)
            unsigned ah[4], al[4];
            ldaF(ab, kt, XHI + P * 4096 + m * 2048, ah);
            ldaF(ab, kt, XLO + P * 4096 + m * 2048, al);
#pragma unroll
            for (int g = 0; g < 4; g++) {
                unsigned bl[2];
                ldbF(ab, wlq, kt, W1LO + g * 8192, bl);
                mma_bf16(zc[g], ah, fW1[kt][g]);
                mma_bf16(zc[g], al, fW1[kt][g]);
                mma_bf16(zc[g], ah, bl);
            }
        }
#pragma unroll
        for (int kt = 0; kt < 4; kt++) {            // h1 part (K=64)
            unsigned ah[4], al[4];
            ldaF(ab, kt, H1HI + Q * 4096 + m * 2048, ah);
            ldaF(ab, kt, H1LO + Q * 4096 + m * 2048, al);
#pragma unroll
            for (int g = 0; g < 4; g++) {
                unsigned bl[2];
                ldbF(ab, wlq, kt, U1LO + g * 8192, bl);
                mma_bf16(zc[g], ah, fU1[kt][g]);
                mma_bf16(zc[g], al, fU1[kt][g]);
                mma_bf16(zc[g], ah, bl);
            }
        }
#pragma unroll
        for (int hh = 0; hh < 2; hh++) {
            const int ci = m * 4 + hh * 2;
            float zi = zc[0][hh*2], zf = zc[1][hh*2], zg = zc[2][hh*2], zo = zc[3][hh*2];
            cs[ci] = sigf(zf) * cs[ci] + sigf(zi) * tanha(zg);
            float hv0 = sigf(zo) * tanha(cs[ci]);
            zi = zc[0][hh*2+1]; zf = zc[1][hh*2+1]; zg = zc[2][hh*2+1]; zo = zc[3][hh*2+1];
            cs[ci+1] = sigf(zf) * cs[ci+1] + sigf(zi) * tanha(zg);
            float hv1 = sigf(zo) * tanha(cs[ci+1]);
            float a0 = bfv(hv0), a1 = bfv(hv1);
            stsw(hsb + (H1HI + P * 4096 + m * 2048 + hh * 1024), pack2(a0, a1));
            stsw(hsb + (H1LO + P * 4096 + m * 2048 + hh * 1024), pack2(hv0 - a0, hv1 - a1));
        }
    }
}

// ---------------- layer 2 step (group B), parity P ----------------
template<int P, bool FIN>
__device__ __forceinline__ void layer2_step(
    char* SM, const unsigned* ab, unsigned wlq, unsigned hsb,
    const unsigned (*fW2)[4][2], const unsigned (*fU2)[4][2],
    const float (*bi)[2], float* cs, int qid, int uu0)
{
    constexpr int Q = P ^ 1;
#pragma unroll
    for (int m = 0; m < 2; m++) {
        float zc[4][4];
#pragma unroll
        for (int g = 0; g < 4; g++) {
            zc[g][0] = bi[g][0]; zc[g][1] = bi[g][1];
            zc[g][2] = bi[g][0]; zc[g][3] = bi[g][1];
        }
#pragma unroll
        for (int kt = 0; kt < 4; kt++) {
            unsigned ah[4], al[4];
            ldaF(ab, kt, H1HI + Q * 4096 + m * 2048, ah);
            ldaF(ab, kt, H1LO + Q * 4096 + m * 2048, al);
#pragma unroll
            for (int g = 0; g < 4; g++) {
                unsigned bl[2];
                ldbF(ab, wlq, kt, W2LO + g * 8192, bl);
                mma_bf16(zc[g], ah, fW2[kt][g]);
                mma_bf16(zc[g], al, fW2[kt][g]);
                mma_bf16(zc[g], ah, bl);
            }
            ldaF(ab, kt, H2HI + P * 4096 + m * 2048, ah);
            ldaF(ab, kt, H2LO + P * 4096 + m * 2048, al);
#pragma unroll
            for (int g = 0; g < 4; g++) {
                unsigned bl[2];
                ldbF(ab, wlq, kt, U2LO + g * 8192, bl);
                mma_bf16(zc[g], ah, fU2[kt][g]);
                mma_bf16(zc[g], al, fU2[kt][g]);
                mma_bf16(zc[g], ah, bl);
            }
        }
#pragma unroll
        for (int hh = 0; hh < 2; hh++) {
            const int ci = m * 4 + hh * 2;
            float zi = zc[0][hh*2], zf = zc[1][hh*2], zg = zc[2][hh*2], zo = zc[3][hh*2];
            cs[ci] = sigf(zf) * cs[ci] + sigf(zi) * tanha(zg);
            float hv0 = sigf(zo) * tanha(cs[ci]);
            zi = zc[0][hh*2+1]; zf = zc[1][hh*2+1]; zg = zc[2][hh*2+1]; zo = zc[3][hh*2+1];
            cs[ci+1] = sigf(zf) * cs[ci+1] + sigf(zi) * tanha(zg);
            float hv1 = sigf(zo) * tanha(cs[ci+1]);
            float a0 = bfv(hv0), a1 = bfv(hv1);
            stsw(hsb + (H2HI + Q * 4096 + m * 2048 + hh * 1024), pack2(a0, a1));
            stsw(hsb + (H2LO + Q * 4096 + m * 2048 + hh * 1024), pack2(hv0 - a0, hv1 - a1));
            if (FIN) {
                const int r = qid + 16 * m + 8 * hh;
                float* dst = (float*)(SM + H2F) + r * 64 + uu0;
                dst[0] = hv0; dst[1] = hv1;
            }
        }
    }
}

template<int DP>
__device__ __forceinline__ void stage_x(char* SM, const float* xg, int bglob, int wg_tid, int t)
{
    int row = wg_tid >> 3, f4 = wg_tid & 7;
    float4 v = *(const float4*)(xg + ((size_t)(bglob + row) * T_STEPS + t) * 32 + f4 * 4);
    float a0 = bfv(v.x), a1 = bfv(v.y), a2 = bfv(v.z), a3 = bfv(v.w);
    sts32(SM, XHI + DP * 4096, row, f4 * 4,     pack2(a0, a1));
    sts32(SM, XHI + DP * 4096, row, f4 * 4 + 2, pack2(a2, a3));
    sts32(SM, XLO + DP * 4096, row, f4 * 4,     pack2(v.x - a0, v.y - a1));
    sts32(SM, XLO + DP * 4096, row, f4 * 4 + 2, pack2(v.z - a2, v.w - a3));
}

__global__ void __launch_bounds__(NTH, 1)
lstm_mma(const float* __restrict__ xg,
         const float* __restrict__ W1g, const float* __restrict__ U1g,
         const float* __restrict__ b1g, const float* __restrict__ W2g,
         const float* __restrict__ U2g, const float* __restrict__ b2g,
         const float* __restrict__ Wdg, const float* __restrict__ bdg,
         const float* __restrict__ Wog, const float* __restrict__ bog,
         float* __restrict__ outg)
{
    extern __shared__ __align__(16) char SM[];
    const int tid  = threadIdx.x;
    const int w    = tid >> 5;
    const int lane = tid & 31;
    const int qid  = lane >> 2;
    const int rid  = lane & 3;
    const int grp  = w >> 3;
    const int wl   = w & 7;
    const int wg_tid = tid & 255;
    const int w8q  = wl * 8 + qid;
    const int uu0  = wl * 8 + rid * 2;
    const int bglob = blockIdx.x * BB;

    for (int i = tid; i < 32 * 256; i += NTH) {
        int k = i >> 8, j = i & 255;
        float v = W1g[i], hf = bfv(v);
        unsigned off = swz((unsigned)(j * 128 + k * 2));
        *(__nv_bfloat16*)(SM + W1HI + off) = __float2bfloat16(hf);
        *(__nv_bfloat16*)(SM + W1LO + off) = __float2bfloat16(v - hf);
    }
    for (int i = tid; i < 64 * 256; i += NTH) {
        int k = i >> 8, j = i & 255;
        unsigned off = swz((unsigned)(j * 128 + k * 2));
        float v = U1g[i];
        *(__nv_bfloat16*)(SM + U1LO + off) = __float2bfloat16(v - bfv(v));
        v = W2g[i];
        *(__nv_bfloat16*)(SM + W2LO + off) = __float2bfloat16(v - bfv(v));
        v = U2g[i];
        *(__nv_bfloat16*)(SM + U2LO + off) = __float2bfloat16(v - bfv(v));
    }
    for (int i = tid; i < 8192; i += NTH) ((unsigned*)(SM + H1HI))[i] = 0;
    if (tid < 256) stage_x<0>(SM, xg, bglob, tid, 0);

    unsigned fA[4][4][2], fB[4][4][2];
    float bi[4][2];
    {
        const float* Ma = (grp == 0) ? U1g : W2g;
        const float* Mb = (grp == 0) ? W1g : U2g;
        const int ktb = (grp == 0) ? 2 : 4;
#pragma unroll
        for (int kt = 0; kt < 4; kt++)
#pragma unroll
            for (int g = 0; g < 4; g++) {
                const int k0 = kt * 16 + rid * 2, n = g * 64 + w8q;
                fA[kt][g][0] = pack2(bfv(Ma[k0 * 256 + n]),       bfv(Ma[(k0 + 1) * 256 + n]));
                fA[kt][g][1] = pack2(bfv(Ma[(k0 + 8) * 256 + n]), bfv(Ma[(k0 + 9) * 256 + n]));
                if (kt < ktb) {
                    fB[kt][g][0] = pack2(bfv(Mb[k0 * 256 + n]),       bfv(Mb[(k0 + 1) * 256 + n]));
                    fB[kt][g][1] = pack2(bfv(Mb[(k0 + 8) * 256 + n]), bfv(Mb[(k0 + 9) * 256 + n]));
                }
            }
        const float* bgp = (grp == 0) ? b1g : b2g;
#pragma unroll
        for (int g = 0; g < 4; g++) {
            bi[g][0] = bgp[g * 64 + uu0]; bi[g][1] = bgp[g * 64 + uu0 + 1];
        }
    }

    const unsigned smb = (unsigned)__cvta_generic_to_shared(SM);
    unsigned ab[8];
#pragma unroll
    for (int kt = 0; kt < 4; kt++)
#pragma unroll
        for (int o = 0; o < 2; o++)
            ab[kt * 2 + o] = smb + qid * 128 + rid * 4 + (((unsigned)(kt * 32 + o * 16)) ^ (qid * 16));
    const unsigned wlq = wl * 1024;
    const unsigned hsb = smb + qid * 128 + rid * 4 + (((unsigned)(wl * 16)) ^ (qid * 16));

    float cs[8];
#pragma unroll
    for (int i = 0; i < 8; i++) cs[i] = 0.0f;

    __syncthreads();

    for (int it = 0; it < T_STEPS / 2; it++) {
        const int i0 = 2 * it;
        if (grp == 0) {
            stage_x<1>(SM, xg, bglob, wg_tid, i0 + 1);
            layer1_step<0>(ab, wlq, hsb,
                           (const unsigned(*)[4][2])fA, (const unsigned(*)[4][2])fB,
                           (const float(*)[2])bi, cs);
        } else if (it > 0) {
            layer2_step<0, false>(SM, ab, wlq, hsb,
                                  (const unsigned(*)[4][2])fA, (const unsigned(*)[4][2])fB,
                                  (const float(*)[2])bi, cs, qid, uu0);
        }
        __syncthreads();
        if (grp == 0) {
            if (it < T_STEPS / 2 - 1)
                stage_x<0>(SM, xg, bglob, wg_tid, i0 + 2);
            layer1_step<1>(ab, wlq, hsb,
                           (const unsigned(*)[4][2])fA, (const unsigned(*)[4][2])fB,
                           (const float(*)[2])bi, cs);
        } else {
            layer2_step<1, false>(SM, ab, wlq, hsb,
                                  (const unsigned(*)[4][2])fA, (const unsigned(*)[4][2])fB,
                                  (const float(*)[2])bi, cs, qid, uu0);
        }
        __syncthreads();
    }
    if (grp == 1)
        layer2_step<0, true>(SM, ab, wlq, hsb,
                             (const unsigned(*)[4][2])fA, (const unsigned(*)[4][2])fB,
                             (const float(*)[2])bi, cs, qid, uu0);
    __syncthreads();

    // ---------- dense head 1 (fp32, exact sigmoid via ex2+rcp) ----------
    {
        const float* h2f = (const float*)(SM + H2F);
        float* ds = (float*)(SM + H1HI);
        const int uu = tid & 63, rg = tid >> 6;
        const float bdv = bdg[uu];
#pragma unroll
        for (int r = 0; r < 4; r++) {
            int row = rg * 4 + r;
            float a = bdv;
#pragma unroll 8
            for (int k = 0; k < 64; k++)
                a += h2f[row * 64 + k] * Wdg[k * 64 + uu];
            ds[row * 64 + uu] = frcp(1.0f + fexp(-a));
        }
    }
    __syncthreads();
    // ---------- dense head 2 ----------
    {
        const float* ds = (const float*)(SM + H1HI);
        const float bov = bog[0];
        const float wo0 = Wog[lane], wo1 = Wog[lane + 32];
#pragma unroll
        for (int r = 0; r < 2; r++) {
            int row = w * 2 + r;
            float pv = ds[row * 64 + lane] * wo0 + ds[row * 64 + lane + 32] * wo1;
#pragma unroll
            for (int s = 16; s; s >>= 1)
                pv += __shfl_xor_sync(0xffffffffu, pv, s);
            if (lane == 0)
                outg[bglob + row] = frcp(1.0f + fexp(-(pv + bov)));
        }
    }
}

extern "C" void kernel_launch(void* const* d_in, const int* in_sizes, int n_in,
                              void* d_out, int out_size)
{
    const float* x  = (const float*)d_in[0];
    const float* W1 = (const float*)d_in[1];
    const float* U1 = (const float*)d_in[2];
    const float* b1 = (const float*)d_in[3];
    const float* W2 = (const float*)d_in[4];
    const float* U2 = (const float*)d_in[5];
    const float* b2 = (const float*)d_in[6];
    const float* Wd = (const float*)d_in[7];
    const float* bd = (const float*)d_in[8];
    const float* Wo = (const float*)d_in[9];
    const float* bo = (const float*)d_in[10];
    float* out = (float*)d_out;

    cudaFuncSetAttribute(lstm_mma, cudaFuncAttributeMaxDynamicSharedMemorySize, SMEM_BYTES);
    lstm_mma<<<BATCH / BB, NTH, SMEM_BYTES>>>(x, W1, U1, b1, W2, U2, b2,
                                              Wd, bd, Wo, bo, out);
}